// round 1
// baseline (speedup 1.0000x reference)
#include <cuda_runtime.h>
#include <math.h>

// ---------------------------------------------------------------------------
// Problem constants
// ---------------------------------------------------------------------------
#define NB     4
#define LSEQ   8192
#define CD     256          // d_model
#define NH     8            // heads
#define HD     32           // head dim
#define MTOT   (NB * LSEQ)  // 32768 rows

// ---------------------------------------------------------------------------
// Scratch (device globals: allocation-free, graph-capture safe)
// ---------------------------------------------------------------------------
__device__ float g_q[(size_t)MTOT * CD];        // Q (elu+1), then attn out in-place
__device__ float g_k[(size_t)MTOT * CD];        // K (elu+1), then msg / msg_ln
__device__ float g_v[(size_t)MTOT * CD];        // V, then msg2
__device__ float g_h[(size_t)MTOT * 2 * CD];    // MLP hidden
__device__ float g_KV[NB * NH * HD * HD];       // per (n,h) 32x32
__device__ float g_Ksum[NB * NH * HD];          // per (n,h) 32

// ---------------------------------------------------------------------------
// Generic SGEMM: C[m,n] = act( sum_k A[m,k] * W[n,k] )
//   A = [A1 | A2] split at K1 (concat support; A2==nullptr -> plain, K1==K)
//   Tiles: 128x128x16, 256 threads, 8x8 per-thread microtile.
// ---------------------------------------------------------------------------
enum { ACT_NONE = 0, ACT_ELU1 = 1, ACT_RELU = 2 };

template <int ACT>
__global__ void __launch_bounds__(256)
gemm_kernel(const float* __restrict__ A1, const float* __restrict__ A2,
            int K1, int K,
            const float* __restrict__ W, float* __restrict__ C, int Ncols)
{
    __shared__ float As[16][128];
    __shared__ float Bs[16][128];

    const int m0  = blockIdx.y * 128;
    const int n0  = blockIdx.x * 128;
    const int tid = threadIdx.x;
    const int tx  = tid & 15;       // 0..15 -> n
    const int ty  = tid >> 4;       // 0..15 -> m

    const int lm = tid >> 2;        // 0..63 : row within half-tile
    const int lk = (tid & 3) * 4;   // 0,4,8,12 : k-vector start

    float acc[8][8];
#pragma unroll
    for (int i = 0; i < 8; ++i)
#pragma unroll
        for (int j = 0; j < 8; ++j) acc[i][j] = 0.0f;

    for (int k0 = 0; k0 < K; k0 += 16) {
        // ---- load A tile (128 x 16) ----
#pragma unroll
        for (int p = 0; p < 2; ++p) {
            const int m  = lm + p * 64;
            const int kg = k0 + lk;
            float4 a;
            if (A2 != nullptr && kg >= K1)
                a = *(const float4*)&A2[(size_t)(m0 + m) * (K - K1) + (kg - K1)];
            else
                a = *(const float4*)&A1[(size_t)(m0 + m) * K1 + kg];
            As[lk + 0][m] = a.x;
            As[lk + 1][m] = a.y;
            As[lk + 2][m] = a.z;
            As[lk + 3][m] = a.w;
        }
        // ---- load B tile from W[N,K] (128 x 16) ----
#pragma unroll
        for (int p = 0; p < 2; ++p) {
            const int n  = lm + p * 64;
            const int kg = k0 + lk;
            float4 b = *(const float4*)&W[(size_t)(n0 + n) * K + kg];
            Bs[lk + 0][n] = b.x;
            Bs[lk + 1][n] = b.y;
            Bs[lk + 2][n] = b.z;
            Bs[lk + 3][n] = b.w;
        }
        __syncthreads();

#pragma unroll
        for (int kk = 0; kk < 16; ++kk) {
            float af[8], bf[8];
            *(float4*)&af[0] = *(const float4*)&As[kk][ty * 8];
            *(float4*)&af[4] = *(const float4*)&As[kk][ty * 8 + 4];
            *(float4*)&bf[0] = *(const float4*)&Bs[kk][tx * 8];
            *(float4*)&bf[4] = *(const float4*)&Bs[kk][tx * 8 + 4];
#pragma unroll
            for (int i = 0; i < 8; ++i)
#pragma unroll
                for (int j = 0; j < 8; ++j)
                    acc[i][j] = fmaf(af[i], bf[j], acc[i][j]);
        }
        __syncthreads();
    }

    // ---- epilogue ----
#pragma unroll
    for (int i = 0; i < 8; ++i) {
        const size_t row = (size_t)(m0 + ty * 8 + i) * Ncols + n0;
#pragma unroll
        for (int j = 0; j < 8; ++j) {
            float r = acc[i][j];
            if (ACT == ACT_ELU1) r = (r > 0.0f) ? (r + 1.0f) : expf(r);
            if (ACT == ACT_RELU) r = fmaxf(r, 0.0f);
            C[row + tx * 8 + j] = r;
        }
    }
}

// ---------------------------------------------------------------------------
// Zero KV / Ksum accumulators
// ---------------------------------------------------------------------------
__global__ void zero_kv_kernel()
{
    int i = blockIdx.x * blockDim.x + threadIdx.x;
    if (i < NB * NH * HD * HD) g_KV[i] = 0.0f;
    if (i < NB * NH * HD)      g_Ksum[i] = 0.0f;
}

// ---------------------------------------------------------------------------
// KV reduce: KV[n,h,d,e] = sum_s K[n,s,h,d] * V[n,s,h,e]; Ksum[n,h,d] = sum_s K
// grid.x = NB*NH, grid.y = S/128 chunks, 256 threads
// ---------------------------------------------------------------------------
__global__ void __launch_bounds__(256)
kv_reduce_kernel(const float* __restrict__ Kmat, const float* __restrict__ Vmat)
{
    __shared__ float Ks[128][HD];
    __shared__ float Vs[128][HD];

    const int nh = blockIdx.x;
    const int n  = nh / NH;
    const int h  = nh % NH;
    const int s0 = blockIdx.y * 128;
    const int tid = threadIdx.x;

    const float* Kbase = Kmat + (size_t)n * LSEQ * CD + (size_t)h * HD;
    const float* Vbase = Vmat + (size_t)n * LSEQ * CD + (size_t)h * HD;

    // 128 rows x 8 float4 per matrix = 1024 float4; 4 per thread
    for (int i = tid; i < 128 * 8; i += 256) {
        const int r  = i >> 3;
        const int c4 = (i & 7) * 4;
        const size_t off = (size_t)(s0 + r) * CD + c4;
        *(float4*)&Ks[r][c4] = *(const float4*)&Kbase[off];
        *(float4*)&Vs[r][c4] = *(const float4*)&Vbase[off];
    }
    __syncthreads();

    const int d  = tid >> 3;        // 0..31
    const int e0 = (tid & 7) * 4;   // 0,4,...,28
    float a0 = 0.f, a1 = 0.f, a2 = 0.f, a3 = 0.f, ks = 0.f;

#pragma unroll 4
    for (int s = 0; s < 128; ++s) {
        const float kv = Ks[s][d];
        ks += kv;
        a0 = fmaf(kv, Vs[s][e0 + 0], a0);
        a1 = fmaf(kv, Vs[s][e0 + 1], a1);
        a2 = fmaf(kv, Vs[s][e0 + 2], a2);
        a3 = fmaf(kv, Vs[s][e0 + 3], a3);
    }

    float* KVout = g_KV + ((size_t)nh * HD + d) * HD + e0;
    atomicAdd(&KVout[0], a0);
    atomicAdd(&KVout[1], a1);
    atomicAdd(&KVout[2], a2);
    atomicAdd(&KVout[3], a3);
    if ((tid & 7) == 0) atomicAdd(&g_Ksum[nh * HD + d], ks);
}

// ---------------------------------------------------------------------------
// Attention apply (in-place on Q):
//   out[l, h*32+e] = Z(l,h) * sum_d Q[l,h*32+d] * KV[n,h,d,e]
//   Z = 1/(sum_d Q[l,h*32+d]*Ksum[n,h,d] + 1e-6)
//   (the v/S prescale and *S postscale cancel exactly)
// 64 rows per block, 256 threads (one output channel each).
// ---------------------------------------------------------------------------
__global__ void __launch_bounds__(256)
attn_apply_kernel(float* __restrict__ Q)
{
    __shared__ float KVs[NH * HD * HD];   // 32 KB
    __shared__ float KsumS[NH * HD];
    __shared__ float Qs[CD];
    __shared__ float Zs[NH];

    const int row0 = blockIdx.x * 64;
    const int n    = row0 / LSEQ;         // 64 | 8192, so one batch per block
    const int tid  = threadIdx.x;
    const int h    = tid >> 5;
    const int e    = tid & 31;

    const float* KVg = g_KV + (size_t)n * NH * HD * HD;
    for (int i = tid; i < NH * HD * HD / 4; i += 256)
        *(float4*)&KVs[i * 4] = *(const float4*)&KVg[i * 4];
    KsumS[tid] = g_Ksum[n * NH * HD + tid];
    __syncthreads();

    for (int r = 0; r < 64; ++r) {
        float* qrow = Q + (size_t)(row0 + r) * CD;
        Qs[tid] = qrow[tid];
        __syncthreads();

        if (e == 0) {
            float s = 0.0f;
#pragma unroll
            for (int d = 0; d < HD; ++d)
                s = fmaf(Qs[h * HD + d], KsumS[h * HD + d], s);
            Zs[h] = 1.0f / (s + 1e-6f);
        }
        __syncthreads();

        float acc = 0.0f;
#pragma unroll
        for (int d = 0; d < HD; ++d)
            acc = fmaf(Qs[h * HD + d], KVs[(h * HD + d) * HD + e], acc);
        qrow[tid] = acc * Zs[h];
        __syncthreads();
    }
}

// ---------------------------------------------------------------------------
// LayerNorm (warp per row of 256). RESIDUAL: out = x + LN(data)
// ---------------------------------------------------------------------------
template <bool RESIDUAL>
__global__ void __launch_bounds__(256)
ln_kernel(const float* __restrict__ src, const float* __restrict__ x,
          float* __restrict__ dst,
          const float* __restrict__ g, const float* __restrict__ b)
{
    const int row  = blockIdx.x * 8 + threadIdx.y;
    const int lane = threadIdx.x;
    const float* p = src + (size_t)row * CD;

    float v[8];
    float s = 0.0f;
#pragma unroll
    for (int i = 0; i < 8; ++i) {
        v[i] = p[i * 32 + lane];
        s += v[i];
    }
#pragma unroll
    for (int o = 16; o > 0; o >>= 1) s += __shfl_xor_sync(0xffffffff, s, o);
    const float mu = s * (1.0f / CD);

    float vs = 0.0f;
#pragma unroll
    for (int i = 0; i < 8; ++i) {
        const float d = v[i] - mu;
        vs = fmaf(d, d, vs);
    }
#pragma unroll
    for (int o = 16; o > 0; o >>= 1) vs += __shfl_xor_sync(0xffffffff, vs, o);
    const float rstd = rsqrtf(vs * (1.0f / CD) + 1e-7f);

    float* q = dst + (size_t)row * CD;
#pragma unroll
    for (int i = 0; i < 8; ++i) {
        const int c = i * 32 + lane;
        float r = (v[i] - mu) * rstd * g[c] + b[c];
        if (RESIDUAL) r += x[(size_t)row * CD + c];
        q[c] = r;
    }
}

// ---------------------------------------------------------------------------
// Launch
// ---------------------------------------------------------------------------
extern "C" void kernel_launch(void* const* d_in, const int* in_sizes, int n_in,
                              void* d_out, int out_size)
{
    const float* x      = (const float*)d_in[0];
    const float* source = (const float*)d_in[1];
    const float* Wq     = (const float*)d_in[2];
    const float* Wk     = (const float*)d_in[3];
    const float* Wv     = (const float*)d_in[4];
    const float* Wmerge = (const float*)d_in[5];
    const float* Wmlp1  = (const float*)d_in[6];
    const float* Wmlp2  = (const float*)d_in[7];
    const float* ln1_g  = (const float*)d_in[8];
    const float* ln1_b  = (const float*)d_in[9];
    const float* ln2_g  = (const float*)d_in[10];
    const float* ln2_b  = (const float*)d_in[11];
    float* out = (float*)d_out;

    float *q, *k, *v, *h, *kvp, *ksp;
    cudaGetSymbolAddress((void**)&q,   g_q);
    cudaGetSymbolAddress((void**)&k,   g_k);
    cudaGetSymbolAddress((void**)&v,   g_v);
    cudaGetSymbolAddress((void**)&h,   g_h);
    (void)kvp; (void)ksp;

    const dim3 g256(2, MTOT / 128);   // N=256 GEMMs
    const dim3 g512(4, MTOT / 128);   // N=512 GEMM

    // Q = elu(x Wq^T)+1 ; K = elu(src Wk^T)+1 ; V = src Wv^T
    gemm_kernel<ACT_ELU1><<<g256, 256>>>(x,      nullptr, CD, CD, Wq, q, CD);
    gemm_kernel<ACT_ELU1><<<g256, 256>>>(source, nullptr, CD, CD, Wk, k, CD);
    gemm_kernel<ACT_NONE><<<g256, 256>>>(source, nullptr, CD, CD, Wv, v, CD);

    // KV / Ksum reduction
    zero_kv_kernel<<<(NB * NH * HD * HD + 255) / 256, 256>>>();
    kv_reduce_kernel<<<dim3(NB * NH, LSEQ / 128), 256>>>(k, v);

    // attention apply, in place on q
    attn_apply_kernel<<<MTOT / 64, 256>>>(q);

    // msg = attn @ Wmerge^T  -> k buffer; then LN1 in place
    gemm_kernel<ACT_NONE><<<g256, 256>>>(q, nullptr, CD, CD, Wmerge, k, CD);
    ln_kernel<false><<<MTOT / 8, dim3(32, 8)>>>(k, nullptr, k, ln1_g, ln1_b);

    // h = relu([x | msg] @ Wmlp1^T)
    gemm_kernel<ACT_RELU><<<g512, 256>>>(x, k, CD, 2 * CD, Wmlp1, h, 2 * CD);

    // msg2 = h @ Wmlp2^T -> v buffer; out = x + LN2(msg2)
    gemm_kernel<ACT_NONE><<<g256, 256>>>(h, nullptr, 2 * CD, 2 * CD, Wmlp2, v, CD);
    ln_kernel<true><<<MTOT / 8, dim3(32, 8)>>>(v, x, out, ln2_g, ln2_b);
}

// round 3
// speedup vs baseline: 2.1298x; 2.1298x over previous
#include <cuda_runtime.h>
#include <cuda_bf16.h>
#include <math.h>
#include <stdint.h>

// ---------------------------------------------------------------------------
// Problem constants
// ---------------------------------------------------------------------------
#define NB     4
#define LSEQ   8192
#define CD     256          // d_model
#define NH     8            // heads
#define HD     32           // head dim
#define MTOT   (NB * LSEQ)  // 32768 rows

// ---------------------------------------------------------------------------
// Scratch (device globals: allocation-free, graph-capture safe)
// ---------------------------------------------------------------------------
__device__ float g_q[(size_t)MTOT * CD];        // Q (elu+1), then attn out in-place
__device__ float g_k[(size_t)MTOT * CD];        // K (elu+1), then msg / msg_ln
__device__ float g_v[(size_t)MTOT * CD];        // V, then msg2
__device__ float g_h[(size_t)MTOT * 2 * CD];    // MLP hidden
__device__ float g_KV[NB * NH * HD * HD];       // per (n,h) 32x32
__device__ float g_Ksum[NB * NH * HD];          // per (n,h) 32

// ---------------------------------------------------------------------------
// mma.sync bf16 GEMM with hi/lo split (fp32-grade accuracy)
//   C[m,n] = act( sum_k A[m,k] * W[n,k] ),  A = [A1 | A2] split at K1
//   Tile: BM=128, BN=128, BK=32 (fp32 k per tile); 8 warps (2x4), warp 64x32.
// ---------------------------------------------------------------------------
enum { ACT_NONE = 0, ACT_ELU1 = 1, ACT_RELU = 2 };

#define BK    32
#define ROWE  40          // padded smem row stride in bf16 elements (80B)

__device__ __forceinline__ uint32_t smem_u32(const void* p) {
    return (uint32_t)__cvta_generic_to_shared(p);
}

__device__ __forceinline__ void ldmx4(uint32_t* r, uint32_t addr) {
    asm volatile("ldmatrix.sync.aligned.m8n8.x4.shared.b16 {%0,%1,%2,%3}, [%4];"
                 : "=r"(r[0]), "=r"(r[1]), "=r"(r[2]), "=r"(r[3]) : "r"(addr));
}

__device__ __forceinline__ void mma16816(float* c, const uint32_t* a,
                                         uint32_t b0, uint32_t b1) {
    asm volatile(
        "mma.sync.aligned.m16n8k16.row.col.f32.bf16.bf16.f32 "
        "{%0,%1,%2,%3}, {%4,%5,%6,%7}, {%8,%9}, {%0,%1,%2,%3};"
        : "+f"(c[0]), "+f"(c[1]), "+f"(c[2]), "+f"(c[3])
        : "r"(a[0]), "r"(a[1]), "r"(a[2]), "r"(a[3]), "r"(b0), "r"(b1));
}

// split fp32x4 -> bf16 hi/lo, store 8B each into padded smem tile
__device__ __forceinline__ void cvt_hilo(__nv_bfloat16* sh, __nv_bfloat16* sl,
                                         int r, int c, float4 v) {
    float2 p0 = make_float2(v.x, v.y);
    float2 p1 = make_float2(v.z, v.w);
    __nv_bfloat162 h0 = __float22bfloat162_rn(p0);
    __nv_bfloat162 h1 = __float22bfloat162_rn(p1);
    float2 r0 = make_float2(v.x - __bfloat162float(h0.x), v.y - __bfloat162float(h0.y));
    float2 r1 = make_float2(v.z - __bfloat162float(h1.x), v.w - __bfloat162float(h1.y));
    __nv_bfloat162 l0 = __float22bfloat162_rn(r0);
    __nv_bfloat162 l1 = __float22bfloat162_rn(r1);
    uint2 H, L;
    H.x = *(uint32_t*)&h0; H.y = *(uint32_t*)&h1;
    L.x = *(uint32_t*)&l0; L.y = *(uint32_t*)&l1;
    *(uint2*)(sh + r * ROWE + c) = H;
    *(uint2*)(sl + r * ROWE + c) = L;
}

template <int ACT>
__global__ void __launch_bounds__(256, 2)
gemm_bf16(const float* __restrict__ A1, const float* __restrict__ A2,
          int K1, int K, const float* __restrict__ W,
          float* __restrict__ C, int NT)
{
    __shared__ __nv_bfloat16 sAh[128 * ROWE];
    __shared__ __nv_bfloat16 sAl[128 * ROWE];
    __shared__ __nv_bfloat16 sBh[128 * ROWE];
    __shared__ __nv_bfloat16 sBl[128 * ROWE];

    const int tid  = threadIdx.x;
    const int wid  = tid >> 5;
    const int lane = tid & 31;
    const int m0   = blockIdx.y * 128;
    const int n0   = blockIdx.x * 128;

    const int wm = (wid >> 2) * 64;   // warp m offset (0/64)
    const int wn = (wid & 3) * 32;    // warp n offset (0..96)

    const uint32_t baseAh = smem_u32(sAh);
    const uint32_t baseAl = smem_u32(sAl);
    const uint32_t baseBh = smem_u32(sBh);
    const uint32_t baseBl = smem_u32(sBl);

    // ldmatrix per-thread row/col pieces (element units)
    const int aRow  = wm + (lane & 15);
    const int aHalf = ((lane >> 4) & 1) * 8;
    const int bRow  = wn + (lane & 7) + ((lane >> 4) & 1) * 8;
    const int bHalf = ((lane >> 3) & 1) * 8;

    // gmem load mapping: 2 threads per row, 4 float4 each (row x 32 floats)
    const int lr = tid >> 1;
    const int lc = (tid & 1) * 16;

    float acc[4][4][4];
#pragma unroll
    for (int i = 0; i < 4; ++i)
#pragma unroll
        for (int j = 0; j < 4; ++j)
#pragma unroll
            for (int r = 0; r < 4; ++r) acc[i][j][r] = 0.0f;

    const int KT = K / BK;
    for (int kt = 0; kt < KT; ++kt) {
        const int kg0 = kt * BK;
        // --- A part select (concat boundary K1 is a multiple of BK) ---
        const float* Ap; int lda, kb;
        if (A2 != nullptr && kg0 >= K1) { Ap = A2; lda = K - K1; kb = kg0 - K1; }
        else                            { Ap = A1; lda = K1;     kb = kg0; }

        // --- load + convert A tile (128 x 32 fp32) ---
        {
            const float* src = Ap + (size_t)(m0 + lr) * lda + kb + lc;
            float4 v0 = *(const float4*)(src + 0);
            float4 v1 = *(const float4*)(src + 4);
            float4 v2 = *(const float4*)(src + 8);
            float4 v3 = *(const float4*)(src + 12);
            cvt_hilo(sAh, sAl, lr, lc + 0,  v0);
            cvt_hilo(sAh, sAl, lr, lc + 4,  v1);
            cvt_hilo(sAh, sAl, lr, lc + 8,  v2);
            cvt_hilo(sAh, sAl, lr, lc + 12, v3);
        }
        // --- load + convert B tile (W rows n0..n0+127, 32 fp32) ---
        {
            const float* src = W + (size_t)(n0 + lr) * K + kg0 + lc;
            float4 v0 = *(const float4*)(src + 0);
            float4 v1 = *(const float4*)(src + 4);
            float4 v2 = *(const float4*)(src + 8);
            float4 v3 = *(const float4*)(src + 12);
            cvt_hilo(sBh, sBl, lr, lc + 0,  v0);
            cvt_hilo(sBh, sBl, lr, lc + 4,  v1);
            cvt_hilo(sBh, sBl, lr, lc + 8,  v2);
            cvt_hilo(sBh, sBl, lr, lc + 12, v3);
        }
        __syncthreads();

        // --- 3 passes: Ah*Bh, Ah*Bl, Al*Bh ---
#pragma unroll
        for (int p = 0; p < 3; ++p) {
            const uint32_t aB = (p < 2) ? baseAh : baseAl;
            const uint32_t bB = (p == 1) ? baseBl : baseBh;
#pragma unroll
            for (int ks = 0; ks < 2; ++ks) {
                uint32_t af[4][4];
#pragma unroll
                for (int mf = 0; mf < 4; ++mf)
                    ldmx4(af[mf], aB + (uint32_t)(((aRow + mf * 16) * ROWE) + ks * 16 + aHalf) * 2);
                uint32_t bf[2][4];
#pragma unroll
                for (int nf = 0; nf < 2; ++nf)
                    ldmx4(bf[nf], bB + (uint32_t)(((bRow + nf * 16) * ROWE) + ks * 16 + bHalf) * 2);
#pragma unroll
                for (int mf = 0; mf < 4; ++mf)
#pragma unroll
                    for (int nr = 0; nr < 4; ++nr)
                        mma16816(acc[mf][nr], af[mf], bf[nr >> 1][(nr & 1) * 2],
                                 bf[nr >> 1][(nr & 1) * 2 + 1]);
            }
        }
        __syncthreads();
    }

    // --- epilogue ---
    const int g = lane >> 2;       // 0..7
    const int qd = lane & 3;       // 0..3
#pragma unroll
    for (int mf = 0; mf < 4; ++mf) {
#pragma unroll
        for (int nr = 0; nr < 4; ++nr) {
#pragma unroll
            for (int half = 0; half < 2; ++half) {
                const int row = m0 + wm + mf * 16 + g + half * 8;
                const int col = n0 + wn + nr * 8 + qd * 2;
                float v0 = acc[mf][nr][half * 2 + 0];
                float v1 = acc[mf][nr][half * 2 + 1];
                if (ACT == ACT_ELU1) {
                    v0 = (v0 > 0.f) ? v0 + 1.f : expf(v0);
                    v1 = (v1 > 0.f) ? v1 + 1.f : expf(v1);
                }
                if (ACT == ACT_RELU) { v0 = fmaxf(v0, 0.f); v1 = fmaxf(v1, 0.f); }
                float2 o; o.x = v0; o.y = v1;
                *(float2*)&C[(size_t)row * NT + col] = o;
            }
        }
    }
}

// ---------------------------------------------------------------------------
// Zero KV / Ksum accumulators
// ---------------------------------------------------------------------------
__global__ void zero_kv_kernel()
{
    int i = blockIdx.x * blockDim.x + threadIdx.x;
    if (i < NB * NH * HD * HD) g_KV[i] = 0.0f;
    if (i < NB * NH * HD)      g_Ksum[i] = 0.0f;
}

// ---------------------------------------------------------------------------
// KV reduce: KV[n,h,d,e] = sum_s K[n,s,h,d] * V[n,s,h,e]; Ksum[n,h,d] = sum_s K
// ---------------------------------------------------------------------------
__global__ void __launch_bounds__(256)
kv_reduce_kernel(const float* __restrict__ Kmat, const float* __restrict__ Vmat)
{
    __shared__ float Ks[128][HD];
    __shared__ float Vs[128][HD];

    const int nh = blockIdx.x;
    const int n  = nh / NH;
    const int h  = nh % NH;
    const int s0 = blockIdx.y * 128;
    const int tid = threadIdx.x;

    const float* Kbase = Kmat + (size_t)n * LSEQ * CD + (size_t)h * HD;
    const float* Vbase = Vmat + (size_t)n * LSEQ * CD + (size_t)h * HD;

    for (int i = tid; i < 128 * 8; i += 256) {
        const int r  = i >> 3;
        const int c4 = (i & 7) * 4;
        const size_t off = (size_t)(s0 + r) * CD + c4;
        *(float4*)&Ks[r][c4] = *(const float4*)&Kbase[off];
        *(float4*)&Vs[r][c4] = *(const float4*)&Vbase[off];
    }
    __syncthreads();

    const int d  = tid >> 3;
    const int e0 = (tid & 7) * 4;
    float a0 = 0.f, a1 = 0.f, a2 = 0.f, a3 = 0.f, ks = 0.f;

#pragma unroll 4
    for (int s = 0; s < 128; ++s) {
        const float kv = Ks[s][d];
        ks += kv;
        a0 = fmaf(kv, Vs[s][e0 + 0], a0);
        a1 = fmaf(kv, Vs[s][e0 + 1], a1);
        a2 = fmaf(kv, Vs[s][e0 + 2], a2);
        a3 = fmaf(kv, Vs[s][e0 + 3], a3);
    }

    float* KVout = g_KV + ((size_t)nh * HD + d) * HD + e0;
    atomicAdd(&KVout[0], a0);
    atomicAdd(&KVout[1], a1);
    atomicAdd(&KVout[2], a2);
    atomicAdd(&KVout[3], a3);
    if ((tid & 7) == 0) atomicAdd(&g_Ksum[nh * HD + d], ks);
}

// ---------------------------------------------------------------------------
// Attention apply (in-place on Q), sync-free row loop; warp == head.
// ---------------------------------------------------------------------------
__global__ void __launch_bounds__(256)
attn_apply_kernel(float* __restrict__ Q)
{
    __shared__ float KVs[NH * HD * HD];
    __shared__ float KsumS[NH * HD];

    const int row0 = blockIdx.x * 64;
    const int n    = row0 / LSEQ;
    const int tid  = threadIdx.x;
    const int h    = tid >> 5;
    const int e    = tid & 31;

    const float* KVg = g_KV + (size_t)n * NH * HD * HD;
    for (int i = tid; i < NH * HD * HD / 4; i += 256)
        ((float4*)KVs)[i] = ((const float4*)KVg)[i];
    KsumS[tid] = g_Ksum[n * NH * HD + tid];
    __syncthreads();

    const float ks = KsumS[tid];
    const float* kvh = &KVs[h * HD * HD];

    for (int r = 0; r < 64; ++r) {
        float* qrow = Q + (size_t)(row0 + r) * CD;
        const float q = qrow[tid];
        float z = q * ks;
#pragma unroll
        for (int o = 16; o > 0; o >>= 1) z += __shfl_xor_sync(0xffffffff, z, o);
        z = 1.0f / (z + 1e-6f);
        float acc = 0.0f;
#pragma unroll
        for (int d = 0; d < HD; ++d)
            acc = fmaf(__shfl_sync(0xffffffff, q, d), kvh[d * HD + e], acc);
        qrow[tid] = acc * z;
    }
}

// ---------------------------------------------------------------------------
// LayerNorm (warp per row of 256). RESIDUAL: out = x + LN(data)
// ---------------------------------------------------------------------------
template <bool RESIDUAL>
__global__ void __launch_bounds__(256)
ln_kernel(const float* __restrict__ src, const float* __restrict__ x,
          float* __restrict__ dst,
          const float* __restrict__ g, const float* __restrict__ b)
{
    const int row  = blockIdx.x * 8 + threadIdx.y;
    const int lane = threadIdx.x;
    const float* p = src + (size_t)row * CD;

    float v[8];
    float s = 0.0f;
#pragma unroll
    for (int i = 0; i < 8; ++i) {
        v[i] = p[i * 32 + lane];
        s += v[i];
    }
#pragma unroll
    for (int o = 16; o > 0; o >>= 1) s += __shfl_xor_sync(0xffffffff, s, o);
    const float mu = s * (1.0f / CD);

    float vs = 0.0f;
#pragma unroll
    for (int i = 0; i < 8; ++i) {
        const float d = v[i] - mu;
        vs = fmaf(d, d, vs);
    }
#pragma unroll
    for (int o = 16; o > 0; o >>= 1) vs += __shfl_xor_sync(0xffffffff, vs, o);
    const float rstd = rsqrtf(vs * (1.0f / CD) + 1e-7f);

    float* q = dst + (size_t)row * CD;
#pragma unroll
    for (int i = 0; i < 8; ++i) {
        const int c = i * 32 + lane;
        float r = (v[i] - mu) * rstd * g[c] + b[c];
        if (RESIDUAL) r += x[(size_t)row * CD + c];
        q[c] = r;
    }
}

// ---------------------------------------------------------------------------
// Launch
// ---------------------------------------------------------------------------
extern "C" void kernel_launch(void* const* d_in, const int* in_sizes, int n_in,
                              void* d_out, int out_size)
{
    const float* x      = (const float*)d_in[0];
    const float* source = (const float*)d_in[1];
    const float* Wq     = (const float*)d_in[2];
    const float* Wk     = (const float*)d_in[3];
    const float* Wv     = (const float*)d_in[4];
    const float* Wmerge = (const float*)d_in[5];
    const float* Wmlp1  = (const float*)d_in[6];
    const float* Wmlp2  = (const float*)d_in[7];
    const float* ln1_g  = (const float*)d_in[8];
    const float* ln1_b  = (const float*)d_in[9];
    const float* ln2_g  = (const float*)d_in[10];
    const float* ln2_b  = (const float*)d_in[11];
    float* out = (float*)d_out;

    float *q, *k, *v, *h;
    cudaGetSymbolAddress((void**)&q, g_q);
    cudaGetSymbolAddress((void**)&k, g_k);
    cudaGetSymbolAddress((void**)&v, g_v);
    cudaGetSymbolAddress((void**)&h, g_h);

    const int GM = MTOT / 128;                 // 256 m-blocks
    const dim3 g256(2, GM);                    // N=256
    const dim3 g512(4, GM);                    // N=512

    // Q = elu(x Wq^T)+1 ; K = elu(src Wk^T)+1 ; V = src Wv^T
    gemm_bf16<ACT_ELU1><<<g256, 256>>>(x,      nullptr, CD, CD, Wq, q, CD);
    gemm_bf16<ACT_ELU1><<<g256, 256>>>(source, nullptr, CD, CD, Wk, k, CD);
    gemm_bf16<ACT_NONE><<<g256, 256>>>(source, nullptr, CD, CD, Wv, v, CD);

    // KV / Ksum reduction
    zero_kv_kernel<<<(NB * NH * HD * HD + 255) / 256, 256>>>();
    kv_reduce_kernel<<<dim3(NB * NH, LSEQ / 128), 256>>>(k, v);

    // attention apply, in place on q
    attn_apply_kernel<<<MTOT / 64, 256>>>(q);

    // msg = attn @ Wmerge^T -> k buffer; then LN1 in place
    gemm_bf16<ACT_NONE><<<g256, 256>>>(q, nullptr, CD, CD, Wmerge, k, CD);
    ln_kernel<false><<<MTOT / 8, dim3(32, 8)>>>(k, nullptr, k, ln1_g, ln1_b);

    // h = relu([x | msg] @ Wmlp1^T)
    gemm_bf16<ACT_RELU><<<g512, 256>>>(x, k, CD, 2 * CD, Wmlp1, h, 2 * CD);

    // msg2 = h @ Wmlp2^T -> v buffer; out = x + LN2(msg2)
    gemm_bf16<ACT_NONE><<<g256, 256>>>(h, nullptr, 2 * CD, 2 * CD, Wmlp2, v, CD);
    ln_kernel<true><<<MTOT / 8, dim3(32, 8)>>>(v, x, out, ln2_g, ln2_b);
}

// round 4
// speedup vs baseline: 2.1657x; 1.0169x over previous
#include <cuda_runtime.h>
#include <cuda_bf16.h>
#include <math.h>
#include <stdint.h>

// ---------------------------------------------------------------------------
// Problem constants
// ---------------------------------------------------------------------------
#define NB     4
#define LSEQ   8192
#define CD     256
#define NH     8
#define HD     32
#define MTOT   (NB * LSEQ)          // 32768
#define MC     ((size_t)MTOT * CD)  // 8388608
#define MC2    ((size_t)MTOT * 2 * CD)

// ---------------------------------------------------------------------------
// Scratch (device globals)
// ---------------------------------------------------------------------------
__device__ float g_q[MC];                 // Q fp32 (attn input)
__device__ float g_k[MC];                 // K fp32, then msg fp32
__device__ float g_v[MC];                 // V fp32, then msg2 fp32
__device__ float g_KV[NB * NH * HD * HD];
__device__ float g_Ksum[NB * NH * HD];

// bf16 hi/lo activations
__device__ __nv_bfloat16 g_xh[MC],  g_xl[MC];    // x
__device__ __nv_bfloat16 g_sh[MC],  g_sl[MC];    // source
__device__ __nv_bfloat16 g_ah[MC],  g_al[MC];    // attn out
__device__ __nv_bfloat16 g_mh[MC],  g_ml[MC];    // msg after LN1
__device__ __nv_bfloat16 g_hh[MC2], g_hl[MC2];   // MLP hidden

// bf16 hi/lo weights
__device__ __nv_bfloat16 g_Wqh[CD * CD], g_Wql[CD * CD];
__device__ __nv_bfloat16 g_Wkh[CD * CD], g_Wkl[CD * CD];
__device__ __nv_bfloat16 g_Wvh[CD * CD], g_Wvl[CD * CD];
__device__ __nv_bfloat16 g_Wmh[CD * CD], g_Wml[CD * CD];
__device__ __nv_bfloat16 g_W1h[2 * CD * 2 * CD], g_W1l[2 * CD * 2 * CD];
__device__ __nv_bfloat16 g_W2h[CD * 2 * CD],     g_W2l[CD * 2 * CD];

// ---------------------------------------------------------------------------
// Helpers
// ---------------------------------------------------------------------------
__device__ __forceinline__ uint32_t smem_u32(const void* p) {
    return (uint32_t)__cvta_generic_to_shared(p);
}
__device__ __forceinline__ void cp16(uint32_t dst, const void* src) {
    asm volatile("cp.async.ca.shared.global [%0], [%1], 16;" :: "r"(dst), "l"(src));
}
__device__ __forceinline__ void cp_commit() {
    asm volatile("cp.async.commit_group;");
}
template <int N>
__device__ __forceinline__ void cp_wait() {
    asm volatile("cp.async.wait_group %0;" :: "n"(N));
}
__device__ __forceinline__ void ldmx4(uint32_t* r, uint32_t addr) {
    asm volatile("ldmatrix.sync.aligned.m8n8.x4.shared.b16 {%0,%1,%2,%3}, [%4];"
                 : "=r"(r[0]), "=r"(r[1]), "=r"(r[2]), "=r"(r[3]) : "r"(addr));
}
__device__ __forceinline__ void mma16816(float* c, const uint32_t* a,
                                         uint32_t b0, uint32_t b1) {
    asm volatile(
        "mma.sync.aligned.m16n8k16.row.col.f32.bf16.bf16.f32 "
        "{%0,%1,%2,%3}, {%4,%5,%6,%7}, {%8,%9}, {%0,%1,%2,%3};"
        : "+f"(c[0]), "+f"(c[1]), "+f"(c[2]), "+f"(c[3])
        : "r"(a[0]), "r"(a[1]), "r"(a[2]), "r"(a[3]), "r"(b0), "r"(b1));
}
__device__ __forceinline__ void split2(float a, float b, uint32_t& H, uint32_t& L) {
    __nv_bfloat162 h; h.x = __float2bfloat16(a); h.y = __float2bfloat16(b);
    __nv_bfloat162 l;
    l.x = __float2bfloat16(a - __bfloat162float(h.x));
    l.y = __float2bfloat16(b - __bfloat162float(h.y));
    H = *(uint32_t*)&h; L = *(uint32_t*)&l;
}

// ---------------------------------------------------------------------------
// fp32 -> bf16 hi/lo conversion (vectorized)
// ---------------------------------------------------------------------------
__global__ void __launch_bounds__(256)
cvt_kernel(const float* __restrict__ src, __nv_bfloat16* __restrict__ h,
           __nv_bfloat16* __restrict__ l, int n4)
{
    int i = blockIdx.x * blockDim.x + threadIdx.x;
    if (i >= n4) return;
    float4 v = ((const float4*)src)[i];
    uint2 H, L;
    split2(v.x, v.y, H.x, L.x);
    split2(v.z, v.w, H.y, L.y);
    ((uint2*)h)[i] = H;
    ((uint2*)l)[i] = L;
}

// ---------------------------------------------------------------------------
// Pipelined bf16 GEMM (hi/lo 3-pass):
//   C[m,n] = act( sum_k A[m,k] * W[n,k] )
//   A = [A1 | A2] concat at K1 (bf16 hi/lo); W bf16 hi/lo.
//   BM=128, BN=128, BK=32; 8 warps (2x4), warp tile 64x32; cp.async 2-stage.
// ---------------------------------------------------------------------------
enum { ACT_NONE = 0, ACT_ELU1 = 1, ACT_RELU = 2 };
enum { OUT_F32 = 0, OUT_HILO = 1 };

#define BK       32
#define ROWB     80            // smem row stride bytes (64B data + 16B pad)
#define TILE_B   (128 * ROWB)  // 10240
#define STAGE_B  (4 * TILE_B)  // 40960
#define AH_OFF   0
#define AL_OFF   TILE_B
#define BH_OFF   (2 * TILE_B)
#define BL_OFF   (3 * TILE_B)
#define SMEM_SZ  (2 * STAGE_B) // 81920

template <int ACT, int OUT>
__global__ void __launch_bounds__(256, 2)
gemm_bf16p(const __nv_bfloat16* __restrict__ Ah1, const __nv_bfloat16* __restrict__ Al1,
           const __nv_bfloat16* __restrict__ Ah2, const __nv_bfloat16* __restrict__ Al2,
           int K1, int K,
           const __nv_bfloat16* __restrict__ Wh, const __nv_bfloat16* __restrict__ Wl,
           float* __restrict__ Cf, __nv_bfloat16* __restrict__ Ch,
           __nv_bfloat16* __restrict__ Cl, int NT)
{
    extern __shared__ char smem[];
    const uint32_t sbase = smem_u32(smem);

    const int tid  = threadIdx.x;
    const int wid  = tid >> 5;
    const int lane = tid & 31;
    const int m0   = blockIdx.y * 128;
    const int n0   = blockIdx.x * 128;

    const int wm = (wid >> 2) * 64;
    const int wn = (wid & 3) * 32;

    // ldmatrix per-thread pieces (element units)
    const int aRow  = wm + (lane & 15);
    const int aHalf = ((lane >> 4) & 1) * 8;
    const int bRow  = wn + (lane & 7) + ((lane >> 4) & 1) * 8;
    const int bHalf = ((lane >> 3) & 1) * 8;

    // gmem->smem mapping: row = tid>>1, 32B half-row per thread
    const int lr  = tid >> 1;
    const int lqb = (tid & 1) * 32;

    float acc[4][4][4];
#pragma unroll
    for (int i = 0; i < 4; ++i)
#pragma unroll
        for (int j = 0; j < 4; ++j)
#pragma unroll
            for (int r = 0; r < 4; ++r) acc[i][j][r] = 0.0f;

    const int KT = K / BK;

    // ---- prefetch one k-tile into stage st ----
    auto prefetch = [&](int kt, int st) {
        const int kg0 = kt * BK;
        const __nv_bfloat16 *pAh, *pAl; int lda, kb;
        if (Ah2 != nullptr && kg0 >= K1) { pAh = Ah2; pAl = Al2; lda = K - K1; kb = kg0 - K1; }
        else                             { pAh = Ah1; pAl = Al1; lda = K1;     kb = kg0; }

        const uint32_t sd = sbase + st * STAGE_B + lr * ROWB + lqb;
        const char* gAh = (const char*)(pAh + (size_t)(m0 + lr) * lda + kb) + lqb;
        const char* gAl = (const char*)(pAl + (size_t)(m0 + lr) * lda + kb) + lqb;
        const char* gBh = (const char*)(Wh + (size_t)(n0 + lr) * K + kg0) + lqb;
        const char* gBl = (const char*)(Wl + (size_t)(n0 + lr) * K + kg0) + lqb;
        cp16(sd + AH_OFF,      gAh);      cp16(sd + AH_OFF + 16, gAh + 16);
        cp16(sd + AL_OFF,      gAl);      cp16(sd + AL_OFF + 16, gAl + 16);
        cp16(sd + BH_OFF,      gBh);      cp16(sd + BH_OFF + 16, gBh + 16);
        cp16(sd + BL_OFF,      gBl);      cp16(sd + BL_OFF + 16, gBl + 16);
        cp_commit();
    };

    prefetch(0, 0);

    for (int kt = 0; kt < KT; ++kt) {
        const int st = kt & 1;
        if (kt + 1 < KT) { prefetch(kt + 1, st ^ 1); cp_wait<1>(); }
        else             { cp_wait<0>(); }
        __syncthreads();

        const uint32_t base = sbase + st * STAGE_B;
#pragma unroll
        for (int p = 0; p < 3; ++p) {
            const uint32_t aB = base + ((p < 2) ? AH_OFF : AL_OFF);
            const uint32_t bB = base + ((p == 1) ? BL_OFF : BH_OFF);
#pragma unroll
            for (int ks = 0; ks < 2; ++ks) {
                uint32_t af[4][4];
#pragma unroll
                for (int mf = 0; mf < 4; ++mf)
                    ldmx4(af[mf], aB + (uint32_t)((aRow + mf * 16) * ROWB) +
                                  (uint32_t)(ks * 16 + aHalf) * 2);
                uint32_t bf[2][4];
#pragma unroll
                for (int nf = 0; nf < 2; ++nf)
                    ldmx4(bf[nf], bB + (uint32_t)((bRow + nf * 16) * ROWB) +
                                  (uint32_t)(ks * 16 + bHalf) * 2);
#pragma unroll
                for (int mf = 0; mf < 4; ++mf)
#pragma unroll
                    for (int nr = 0; nr < 4; ++nr)
                        mma16816(acc[mf][nr], af[mf], bf[nr >> 1][(nr & 1) * 2],
                                 bf[nr >> 1][(nr & 1) * 2 + 1]);
            }
        }
        __syncthreads();
    }

    // ---- epilogue ----
    const int g  = lane >> 2;
    const int qd = lane & 3;
#pragma unroll
    for (int mf = 0; mf < 4; ++mf) {
#pragma unroll
        for (int nr = 0; nr < 4; ++nr) {
#pragma unroll
            for (int half = 0; half < 2; ++half) {
                const int row = m0 + wm + mf * 16 + g + half * 8;
                const int col = n0 + wn + nr * 8 + qd * 2;
                float v0 = acc[mf][nr][half * 2 + 0];
                float v1 = acc[mf][nr][half * 2 + 1];
                if (ACT == ACT_ELU1) {
                    v0 = (v0 > 0.f) ? v0 + 1.f : expf(v0);
                    v1 = (v1 > 0.f) ? v1 + 1.f : expf(v1);
                }
                if (ACT == ACT_RELU) { v0 = fmaxf(v0, 0.f); v1 = fmaxf(v1, 0.f); }
                const size_t off = (size_t)row * NT + col;
                if (OUT == OUT_F32) {
                    float2 o; o.x = v0; o.y = v1;
                    *(float2*)&Cf[off] = o;
                } else {
                    uint32_t H, L;
                    split2(v0, v1, H, L);
                    *(uint32_t*)&Ch[off] = H;
                    *(uint32_t*)&Cl[off] = L;
                }
            }
        }
    }
}

// ---------------------------------------------------------------------------
// Zero KV / Ksum accumulators
// ---------------------------------------------------------------------------
__global__ void zero_kv_kernel()
{
    int i = blockIdx.x * blockDim.x + threadIdx.x;
    if (i < NB * NH * HD * HD) g_KV[i] = 0.0f;
    if (i < NB * NH * HD)      g_Ksum[i] = 0.0f;
}

// ---------------------------------------------------------------------------
// KV reduce
// ---------------------------------------------------------------------------
__global__ void __launch_bounds__(256)
kv_reduce_kernel(const float* __restrict__ Kmat, const float* __restrict__ Vmat)
{
    __shared__ float Ks[128][HD];
    __shared__ float Vs[128][HD];

    const int nh = blockIdx.x;
    const int n  = nh / NH;
    const int h  = nh % NH;
    const int s0 = blockIdx.y * 128;
    const int tid = threadIdx.x;

    const float* Kbase = Kmat + (size_t)n * LSEQ * CD + (size_t)h * HD;
    const float* Vbase = Vmat + (size_t)n * LSEQ * CD + (size_t)h * HD;

    for (int i = tid; i < 128 * 8; i += 256) {
        const int r  = i >> 3;
        const int c4 = (i & 7) * 4;
        const size_t off = (size_t)(s0 + r) * CD + c4;
        *(float4*)&Ks[r][c4] = *(const float4*)&Kbase[off];
        *(float4*)&Vs[r][c4] = *(const float4*)&Vbase[off];
    }
    __syncthreads();

    const int d  = tid >> 3;
    const int e0 = (tid & 7) * 4;
    float a0 = 0.f, a1 = 0.f, a2 = 0.f, a3 = 0.f, ks = 0.f;

#pragma unroll 4
    for (int s = 0; s < 128; ++s) {
        const float kv = Ks[s][d];
        ks += kv;
        a0 = fmaf(kv, Vs[s][e0 + 0], a0);
        a1 = fmaf(kv, Vs[s][e0 + 1], a1);
        a2 = fmaf(kv, Vs[s][e0 + 2], a2);
        a3 = fmaf(kv, Vs[s][e0 + 3], a3);
    }

    float* KVout = g_KV + ((size_t)nh * HD + d) * HD + e0;
    atomicAdd(&KVout[0], a0);
    atomicAdd(&KVout[1], a1);
    atomicAdd(&KVout[2], a2);
    atomicAdd(&KVout[3], a3);
    if ((tid & 7) == 0) atomicAdd(&g_Ksum[nh * HD + d], ks);
}

// ---------------------------------------------------------------------------
// Attention apply: reads Q fp32, writes bf16 hi/lo; warp == head.
// ---------------------------------------------------------------------------
__global__ void __launch_bounds__(256)
attn_apply_kernel(const float* __restrict__ Q,
                  __nv_bfloat16* __restrict__ Oh, __nv_bfloat16* __restrict__ Ol)
{
    __shared__ float KVs[NH * HD * HD];
    __shared__ float KsumS[NH * HD];

    const int row0 = blockIdx.x * 64;
    const int n    = row0 / LSEQ;
    const int tid  = threadIdx.x;
    const int h    = tid >> 5;
    const int e    = tid & 31;

    const float* KVg = g_KV + (size_t)n * NH * HD * HD;
    for (int i = tid; i < NH * HD * HD / 4; i += 256)
        ((float4*)KVs)[i] = ((const float4*)KVg)[i];
    KsumS[tid] = g_Ksum[n * NH * HD + tid];
    __syncthreads();

    const float ks = KsumS[tid];
    const float* kvh = &KVs[h * HD * HD];

    for (int r = 0; r < 64; ++r) {
        const size_t base = (size_t)(row0 + r) * CD;
        const float q = Q[base + tid];
        float z = q * ks;
#pragma unroll
        for (int o = 16; o > 0; o >>= 1) z += __shfl_xor_sync(0xffffffff, z, o);
        z = 1.0f / (z + 1e-6f);
        float acc = 0.0f;
#pragma unroll
        for (int d = 0; d < HD; ++d)
            acc = fmaf(__shfl_sync(0xffffffff, q, d), kvh[d * HD + e], acc);
        const float v = acc * z;
        const __nv_bfloat16 hh = __float2bfloat16(v);
        Oh[base + tid] = hh;
        Ol[base + tid] = __float2bfloat16(v - __bfloat162float(hh));
    }
}

// ---------------------------------------------------------------------------
// LayerNorm variants
// ---------------------------------------------------------------------------
__global__ void __launch_bounds__(256)
ln_hilo_kernel(const float* __restrict__ src,
               __nv_bfloat16* __restrict__ oh, __nv_bfloat16* __restrict__ ol,
               const float* __restrict__ g, const float* __restrict__ b)
{
    const int row  = blockIdx.x * 8 + threadIdx.y;
    const int lane = threadIdx.x;
    const float* p = src + (size_t)row * CD;

    float v[8];
    float s = 0.0f;
#pragma unroll
    for (int i = 0; i < 8; ++i) { v[i] = p[i * 32 + lane]; s += v[i]; }
#pragma unroll
    for (int o = 16; o > 0; o >>= 1) s += __shfl_xor_sync(0xffffffff, s, o);
    const float mu = s * (1.0f / CD);

    float vs = 0.0f;
#pragma unroll
    for (int i = 0; i < 8; ++i) { const float d = v[i] - mu; vs = fmaf(d, d, vs); }
#pragma unroll
    for (int o = 16; o > 0; o >>= 1) vs += __shfl_xor_sync(0xffffffff, vs, o);
    const float rstd = rsqrtf(vs * (1.0f / CD) + 1e-7f);

#pragma unroll
    for (int i = 0; i < 8; ++i) {
        const int c = i * 32 + lane;
        const float r = (v[i] - mu) * rstd * g[c] + b[c];
        const __nv_bfloat16 hh = __float2bfloat16(r);
        oh[(size_t)row * CD + c] = hh;
        ol[(size_t)row * CD + c] = __float2bfloat16(r - __bfloat162float(hh));
    }
}

__global__ void __launch_bounds__(256)
ln_res_kernel(const float* __restrict__ src, const float* __restrict__ x,
              float* __restrict__ dst,
              const float* __restrict__ g, const float* __restrict__ b)
{
    const int row  = blockIdx.x * 8 + threadIdx.y;
    const int lane = threadIdx.x;
    const float* p = src + (size_t)row * CD;

    float v[8];
    float s = 0.0f;
#pragma unroll
    for (int i = 0; i < 8; ++i) { v[i] = p[i * 32 + lane]; s += v[i]; }
#pragma unroll
    for (int o = 16; o > 0; o >>= 1) s += __shfl_xor_sync(0xffffffff, s, o);
    const float mu = s * (1.0f / CD);

    float vs = 0.0f;
#pragma unroll
    for (int i = 0; i < 8; ++i) { const float d = v[i] - mu; vs = fmaf(d, d, vs); }
#pragma unroll
    for (int o = 16; o > 0; o >>= 1) vs += __shfl_xor_sync(0xffffffff, vs, o);
    const float rstd = rsqrtf(vs * (1.0f / CD) + 1e-7f);

#pragma unroll
    for (int i = 0; i < 8; ++i) {
        const int c = i * 32 + lane;
        dst[(size_t)row * CD + c] =
            (v[i] - mu) * rstd * g[c] + b[c] + x[(size_t)row * CD + c];
    }
}

// ---------------------------------------------------------------------------
// Launch
// ---------------------------------------------------------------------------
extern "C" void kernel_launch(void* const* d_in, const int* in_sizes, int n_in,
                              void* d_out, int out_size)
{
    const float* x      = (const float*)d_in[0];
    const float* source = (const float*)d_in[1];
    const float* Wq     = (const float*)d_in[2];
    const float* Wk     = (const float*)d_in[3];
    const float* Wv     = (const float*)d_in[4];
    const float* Wmerge = (const float*)d_in[5];
    const float* Wmlp1  = (const float*)d_in[6];
    const float* Wmlp2  = (const float*)d_in[7];
    const float* ln1_g  = (const float*)d_in[8];
    const float* ln1_b  = (const float*)d_in[9];
    const float* ln2_g  = (const float*)d_in[10];
    const float* ln2_b  = (const float*)d_in[11];
    float* out = (float*)d_out;

    float *q, *k, *v;
    __nv_bfloat16 *xh, *xl, *sh, *sl, *ah, *al, *mh, *ml, *hh, *hl;
    __nv_bfloat16 *Wqh, *Wql, *Wkh, *Wkl, *Wvh, *Wvl, *Wmh, *Wml, *W1h, *W1l, *W2h, *W2l;
    cudaGetSymbolAddress((void**)&q, g_q);
    cudaGetSymbolAddress((void**)&k, g_k);
    cudaGetSymbolAddress((void**)&v, g_v);
    cudaGetSymbolAddress((void**)&xh, g_xh);  cudaGetSymbolAddress((void**)&xl, g_xl);
    cudaGetSymbolAddress((void**)&sh, g_sh);  cudaGetSymbolAddress((void**)&sl, g_sl);
    cudaGetSymbolAddress((void**)&ah, g_ah);  cudaGetSymbolAddress((void**)&al, g_al);
    cudaGetSymbolAddress((void**)&mh, g_mh);  cudaGetSymbolAddress((void**)&ml, g_ml);
    cudaGetSymbolAddress((void**)&hh, g_hh);  cudaGetSymbolAddress((void**)&hl, g_hl);
    cudaGetSymbolAddress((void**)&Wqh, g_Wqh); cudaGetSymbolAddress((void**)&Wql, g_Wql);
    cudaGetSymbolAddress((void**)&Wkh, g_Wkh); cudaGetSymbolAddress((void**)&Wkl, g_Wkl);
    cudaGetSymbolAddress((void**)&Wvh, g_Wvh); cudaGetSymbolAddress((void**)&Wvl, g_Wvl);
    cudaGetSymbolAddress((void**)&Wmh, g_Wmh); cudaGetSymbolAddress((void**)&Wml, g_Wml);
    cudaGetSymbolAddress((void**)&W1h, g_W1h); cudaGetSymbolAddress((void**)&W1l, g_W1l);
    cudaGetSymbolAddress((void**)&W2h, g_W2h); cudaGetSymbolAddress((void**)&W2l, g_W2l);

    static bool smem_set = false;
    if (!smem_set) {
        cudaFuncSetAttribute((const void*)gemm_bf16p<ACT_ELU1, OUT_F32>,
                             cudaFuncAttributeMaxDynamicSharedMemorySize, SMEM_SZ);
        cudaFuncSetAttribute((const void*)gemm_bf16p<ACT_NONE, OUT_F32>,
                             cudaFuncAttributeMaxDynamicSharedMemorySize, SMEM_SZ);
        cudaFuncSetAttribute((const void*)gemm_bf16p<ACT_RELU, OUT_HILO>,
                             cudaFuncAttributeMaxDynamicSharedMemorySize, SMEM_SZ);
        smem_set = true;
    }

    // ---- conversions (inputs + weights) ----
    cvt_kernel<<<(int)(MC / 4 / 256), 256>>>(x,      xh, xl, (int)(MC / 4));
    cvt_kernel<<<(int)(MC / 4 / 256), 256>>>(source, sh, sl, (int)(MC / 4));
    cvt_kernel<<<CD * CD / 4 / 256, 256>>>(Wq, Wqh, Wql, CD * CD / 4);
    cvt_kernel<<<CD * CD / 4 / 256, 256>>>(Wk, Wkh, Wkl, CD * CD / 4);
    cvt_kernel<<<CD * CD / 4 / 256, 256>>>(Wv, Wvh, Wvl, CD * CD / 4);
    cvt_kernel<<<CD * CD / 4 / 256, 256>>>(Wmerge, Wmh, Wml, CD * CD / 4);
    cvt_kernel<<<4 * CD * CD / 4 / 256, 256>>>(Wmlp1, W1h, W1l, 4 * CD * CD / 4);
    cvt_kernel<<<2 * CD * CD / 4 / 256, 256>>>(Wmlp2, W2h, W2l, 2 * CD * CD / 4);

    const int GM = MTOT / 128;
    const dim3 g256(2, GM);
    const dim3 g512(4, GM);

    // Q/K/V
    gemm_bf16p<ACT_ELU1, OUT_F32><<<g256, 256, SMEM_SZ>>>(
        xh, xl, nullptr, nullptr, CD, CD, Wqh, Wql, q, nullptr, nullptr, CD);
    gemm_bf16p<ACT_ELU1, OUT_F32><<<g256, 256, SMEM_SZ>>>(
        sh, sl, nullptr, nullptr, CD, CD, Wkh, Wkl, k, nullptr, nullptr, CD);
    gemm_bf16p<ACT_NONE, OUT_F32><<<g256, 256, SMEM_SZ>>>(
        sh, sl, nullptr, nullptr, CD, CD, Wvh, Wvl, v, nullptr, nullptr, CD);

    // KV / Ksum
    zero_kv_kernel<<<(NB * NH * HD * HD + 255) / 256, 256>>>();
    kv_reduce_kernel<<<dim3(NB * NH, LSEQ / 128), 256>>>(k, v);

    // attention apply -> hi/lo
    attn_apply_kernel<<<MTOT / 64, 256>>>(q, ah, al);

    // msg = attn @ Wmerge^T (fp32 into k), LN1 -> hi/lo
    gemm_bf16p<ACT_NONE, OUT_F32><<<g256, 256, SMEM_SZ>>>(
        ah, al, nullptr, nullptr, CD, CD, Wmh, Wml, k, nullptr, nullptr, CD);
    ln_hilo_kernel<<<MTOT / 8, dim3(32, 8)>>>(k, mh, ml, ln1_g, ln1_b);

    // h = relu([x | msg] @ Wmlp1^T) -> hi/lo
    gemm_bf16p<ACT_RELU, OUT_HILO><<<g512, 256, SMEM_SZ>>>(
        xh, xl, mh, ml, CD, 2 * CD, W1h, W1l, nullptr, hh, hl, 2 * CD);

    // msg2 = h @ Wmlp2^T (fp32 into v); out = x + LN2(msg2)
    gemm_bf16p<ACT_NONE, OUT_F32><<<g256, 256, SMEM_SZ>>>(
        hh, hl, nullptr, nullptr, 2 * CD, 2 * CD, W2h, W2l, v, nullptr, nullptr, CD);
    ln_res_kernel<<<MTOT / 8, dim3(32, 8)>>>(v, x, out, ln2_g, ln2_b);
}

// round 5
// speedup vs baseline: 2.8359x; 1.3094x over previous
#include <cuda_runtime.h>
#include <cuda_fp16.h>
#include <math.h>
#include <stdint.h>

// ---------------------------------------------------------------------------
// Problem constants
// ---------------------------------------------------------------------------
#define NB     4
#define LSEQ   8192
#define CD     256
#define NH     8
#define HD     32
#define MTOT   (NB * LSEQ)          // 32768
#define MC     ((size_t)MTOT * CD)  // 8388608
#define MC2    ((size_t)MTOT * 2 * CD)

// ---------------------------------------------------------------------------
// Scratch (device globals)
// ---------------------------------------------------------------------------
__device__ float g_q[MC];                 // Q fp32 (attn input)
__device__ float g_k[MC];                 // K fp32, then msg fp32
__device__ float g_v[MC];                 // V fp32, then msg2 fp32
__device__ float g_KV[NB * NH * HD * HD];
__device__ float g_Ksum[NB * NH * HD];

// fp16 hi/lo activations (A-side operands)
__device__ __half g_xh[MC],  g_xl[MC];    // x
__device__ __half g_sh[MC],  g_sl[MC];    // source
__device__ __half g_ah[MC],  g_al[MC];    // attn out
__device__ __half g_mh[MC],  g_ml[MC];    // msg after LN1
__device__ __half g_hh[MC2], g_hl[MC2];   // MLP hidden

// fp16 weights (B-side, single rounding)
__device__ __half g_Wq16[CD * CD];
__device__ __half g_Wk16[CD * CD];
__device__ __half g_Wv16[CD * CD];
__device__ __half g_Wm16[CD * CD];
__device__ __half g_W116[2 * CD * 2 * CD];
__device__ __half g_W216[CD * 2 * CD];

// ---------------------------------------------------------------------------
// Helpers
// ---------------------------------------------------------------------------
__device__ __forceinline__ uint32_t smem_u32(const void* p) {
    return (uint32_t)__cvta_generic_to_shared(p);
}
__device__ __forceinline__ void cp16(uint32_t dst, const void* src) {
    asm volatile("cp.async.ca.shared.global [%0], [%1], 16;" :: "r"(dst), "l"(src));
}
__device__ __forceinline__ void cp_commit() {
    asm volatile("cp.async.commit_group;");
}
template <int N>
__device__ __forceinline__ void cp_wait() {
    asm volatile("cp.async.wait_group %0;" :: "n"(N));
}
__device__ __forceinline__ void ldmx4(uint32_t* r, uint32_t addr) {
    asm volatile("ldmatrix.sync.aligned.m8n8.x4.shared.b16 {%0,%1,%2,%3}, [%4];"
                 : "=r"(r[0]), "=r"(r[1]), "=r"(r[2]), "=r"(r[3]) : "r"(addr));
}
__device__ __forceinline__ void mma16816(float* c, const uint32_t* a,
                                         uint32_t b0, uint32_t b1) {
    asm volatile(
        "mma.sync.aligned.m16n8k16.row.col.f32.f16.f16.f32 "
        "{%0,%1,%2,%3}, {%4,%5,%6,%7}, {%8,%9}, {%0,%1,%2,%3};"
        : "+f"(c[0]), "+f"(c[1]), "+f"(c[2]), "+f"(c[3])
        : "r"(a[0]), "r"(a[1]), "r"(a[2]), "r"(a[3]), "r"(b0), "r"(b1));
}
// fp32 pair -> fp16 hi + fp16 lo (residual)
__device__ __forceinline__ void split2h(float a, float b, uint32_t& H, uint32_t& L) {
    __half2 h = __floats2half2_rn(a, b);
    float2 f = __half22float2(h);
    __half2 l = __floats2half2_rn(a - f.x, b - f.y);
    H = *(uint32_t*)&h; L = *(uint32_t*)&l;
}

// ---------------------------------------------------------------------------
// Activation conversion: fp32 -> fp16 hi/lo.  blockIdx.y: 0 = x, 1 = source.
// ---------------------------------------------------------------------------
__global__ void __launch_bounds__(256)
cvt_act_kernel(const float* __restrict__ x, const float* __restrict__ src)
{
    const size_t i = (size_t)blockIdx.x * blockDim.x + threadIdx.x;  // float4 idx
    const float* s = blockIdx.y ? src : x;
    __half* oh = blockIdx.y ? g_sh : g_xh;
    __half* ol = blockIdx.y ? g_sl : g_xl;
    float4 v = ((const float4*)s)[i];
    uint2 H, L;
    split2h(v.x, v.y, H.x, L.x);
    split2h(v.z, v.w, H.y, L.y);
    ((uint2*)oh)[i] = H;
    ((uint2*)ol)[i] = L;
}

// ---------------------------------------------------------------------------
// Weight conversion: fp32 -> fp16 (single rounding). 163840 float4 total.
// ---------------------------------------------------------------------------
__global__ void __launch_bounds__(256)
cvt_w_kernel(const float* __restrict__ Wq, const float* __restrict__ Wk,
             const float* __restrict__ Wv, const float* __restrict__ Wm,
             const float* __restrict__ W1, const float* __restrict__ W2)
{
    const int i = blockIdx.x * blockDim.x + threadIdx.x;   // float4 index
    const float* s; __half* d; int j;
    if      (i <  16384) { s = Wq; d = g_Wq16; j = i; }
    else if (i <  32768) { s = Wk; d = g_Wk16; j = i - 16384; }
    else if (i <  49152) { s = Wv; d = g_Wv16; j = i - 32768; }
    else if (i <  65536) { s = Wm; d = g_Wm16; j = i - 49152; }
    else if (i < 131072) { s = W1; d = g_W116; j = i - 65536; }
    else                 { s = W2; d = g_W216; j = i - 131072; }
    float4 v = ((const float4*)s)[j];
    __half2 a = __floats2half2_rn(v.x, v.y);
    __half2 b = __floats2half2_rn(v.z, v.w);
    uint2 o; o.x = *(uint32_t*)&a; o.y = *(uint32_t*)&b;
    ((uint2*)d)[j] = o;
}

// ---------------------------------------------------------------------------
// Pipelined fp16 GEMM, 2-pass hi/lo on A only:
//   C[m,n] = act( sum_k A[m,k] * W[n,k] ),  A=(Ah+Al) fp16, W fp16.
//   BM=128, BN=128, BK=32; 8 warps (2x4), warp tile 64x32; cp.async 2-stage.
// ---------------------------------------------------------------------------
enum { ACT_NONE = 0, ACT_ELU1 = 1, ACT_RELU = 2 };
enum { OUT_F32 = 0, OUT_HILO = 1 };

#define BK       32
#define ROWB     80            // smem row stride bytes (64B data + 16B pad)
#define TILE_B   (128 * ROWB)  // 10240
#define STAGE_B  (3 * TILE_B)  // 30720
#define AH_OFF   0
#define AL_OFF   TILE_B
#define BH_OFF   (2 * TILE_B)
#define SMEM_SZ  (2 * STAGE_B) // 61440

template <int ACT, int OUT>
__global__ void __launch_bounds__(256, 2)
gemm_f16p(const __half* __restrict__ Ah1, const __half* __restrict__ Al1,
          const __half* __restrict__ Ah2, const __half* __restrict__ Al2,
          int K1, int K, const __half* __restrict__ Wh,
          float* __restrict__ Cf, __half* __restrict__ Ch,
          __half* __restrict__ Cl, int NT)
{
    extern __shared__ char smem[];
    const uint32_t sbase = smem_u32(smem);

    const int tid  = threadIdx.x;
    const int wid  = tid >> 5;
    const int lane = tid & 31;
    const int m0   = blockIdx.y * 128;
    const int n0   = blockIdx.x * 128;

    const int wm = (wid >> 2) * 64;
    const int wn = (wid & 3) * 32;

    const int aRow  = wm + (lane & 15);
    const int aHalf = ((lane >> 4) & 1) * 8;
    const int bRow  = wn + (lane & 7) + ((lane >> 4) & 1) * 8;
    const int bHalf = ((lane >> 3) & 1) * 8;

    const int lr  = tid >> 1;
    const int lqb = (tid & 1) * 32;

    float acc[4][4][4];
#pragma unroll
    for (int i = 0; i < 4; ++i)
#pragma unroll
        for (int j = 0; j < 4; ++j)
#pragma unroll
            for (int r = 0; r < 4; ++r) acc[i][j][r] = 0.0f;

    const int KT = K / BK;

    auto prefetch = [&](int kt, int st) {
        const int kg0 = kt * BK;
        const __half *pAh, *pAl; int lda, kb;
        if (Ah2 != nullptr && kg0 >= K1) { pAh = Ah2; pAl = Al2; lda = K - K1; kb = kg0 - K1; }
        else                             { pAh = Ah1; pAl = Al1; lda = K1;     kb = kg0; }

        const uint32_t sd = sbase + st * STAGE_B + lr * ROWB + lqb;
        const char* gAh = (const char*)(pAh + (size_t)(m0 + lr) * lda + kb) + lqb;
        const char* gAl = (const char*)(pAl + (size_t)(m0 + lr) * lda + kb) + lqb;
        const char* gBh = (const char*)(Wh + (size_t)(n0 + lr) * K + kg0) + lqb;
        cp16(sd + AH_OFF, gAh);  cp16(sd + AH_OFF + 16, gAh + 16);
        cp16(sd + AL_OFF, gAl);  cp16(sd + AL_OFF + 16, gAl + 16);
        cp16(sd + BH_OFF, gBh);  cp16(sd + BH_OFF + 16, gBh + 16);
        cp_commit();
    };

    prefetch(0, 0);

    for (int kt = 0; kt < KT; ++kt) {
        const int st = kt & 1;
        if (kt + 1 < KT) { prefetch(kt + 1, st ^ 1); cp_wait<1>(); }
        else             { cp_wait<0>(); }
        __syncthreads();

        const uint32_t base = sbase + st * STAGE_B;
#pragma unroll
        for (int ks = 0; ks < 2; ++ks) {
            // B fragments loaded once, reused by both A passes
            uint32_t bf[2][4];
#pragma unroll
            for (int nf = 0; nf < 2; ++nf)
                ldmx4(bf[nf], base + BH_OFF + (uint32_t)((bRow + nf * 16) * ROWB) +
                              (uint32_t)(ks * 16 + bHalf) * 2);
            uint32_t af[4][4];
            // pass 1: Ah
#pragma unroll
            for (int mf = 0; mf < 4; ++mf)
                ldmx4(af[mf], base + AH_OFF + (uint32_t)((aRow + mf * 16) * ROWB) +
                              (uint32_t)(ks * 16 + aHalf) * 2);
#pragma unroll
            for (int mf = 0; mf < 4; ++mf)
#pragma unroll
                for (int nr = 0; nr < 4; ++nr)
                    mma16816(acc[mf][nr], af[mf], bf[nr >> 1][(nr & 1) * 2],
                             bf[nr >> 1][(nr & 1) * 2 + 1]);
            // pass 2: Al
#pragma unroll
            for (int mf = 0; mf < 4; ++mf)
                ldmx4(af[mf], base + AL_OFF + (uint32_t)((aRow + mf * 16) * ROWB) +
                              (uint32_t)(ks * 16 + aHalf) * 2);
#pragma unroll
            for (int mf = 0; mf < 4; ++mf)
#pragma unroll
                for (int nr = 0; nr < 4; ++nr)
                    mma16816(acc[mf][nr], af[mf], bf[nr >> 1][(nr & 1) * 2],
                             bf[nr >> 1][(nr & 1) * 2 + 1]);
        }
        __syncthreads();
    }

    // ---- epilogue ----
    const int g  = lane >> 2;
    const int qd = lane & 3;
#pragma unroll
    for (int mf = 0; mf < 4; ++mf) {
#pragma unroll
        for (int nr = 0; nr < 4; ++nr) {
#pragma unroll
            for (int half = 0; half < 2; ++half) {
                const int row = m0 + wm + mf * 16 + g + half * 8;
                const int col = n0 + wn + nr * 8 + qd * 2;
                float v0 = acc[mf][nr][half * 2 + 0];
                float v1 = acc[mf][nr][half * 2 + 1];
                if (ACT == ACT_ELU1) {
                    v0 = (v0 > 0.f) ? v0 + 1.f : expf(v0);
                    v1 = (v1 > 0.f) ? v1 + 1.f : expf(v1);
                }
                if (ACT == ACT_RELU) { v0 = fmaxf(v0, 0.f); v1 = fmaxf(v1, 0.f); }
                const size_t off = (size_t)row * NT + col;
                if (OUT == OUT_F32) {
                    float2 o; o.x = v0; o.y = v1;
                    *(float2*)&Cf[off] = o;
                } else {
                    uint32_t H, L;
                    split2h(v0, v1, H, L);
                    *(uint32_t*)&Ch[off] = H;
                    *(uint32_t*)&Cl[off] = L;
                }
            }
        }
    }
}

// ---------------------------------------------------------------------------
// Zero KV / Ksum accumulators
// ---------------------------------------------------------------------------
__global__ void zero_kv_kernel()
{
    int i = blockIdx.x * blockDim.x + threadIdx.x;
    if (i < NB * NH * HD * HD) g_KV[i] = 0.0f;
    if (i < NB * NH * HD)      g_Ksum[i] = 0.0f;
}

// ---------------------------------------------------------------------------
// KV reduce
// ---------------------------------------------------------------------------
__global__ void __launch_bounds__(256)
kv_reduce_kernel(const float* __restrict__ Kmat, const float* __restrict__ Vmat)
{
    __shared__ float Ks[128][HD];
    __shared__ float Vs[128][HD];

    const int nh = blockIdx.x;
    const int n  = nh / NH;
    const int h  = nh % NH;
    const int s0 = blockIdx.y * 128;
    const int tid = threadIdx.x;

    const float* Kbase = Kmat + (size_t)n * LSEQ * CD + (size_t)h * HD;
    const float* Vbase = Vmat + (size_t)n * LSEQ * CD + (size_t)h * HD;

    for (int i = tid; i < 128 * 8; i += 256) {
        const int r  = i >> 3;
        const int c4 = (i & 7) * 4;
        const size_t off = (size_t)(s0 + r) * CD + c4;
        *(float4*)&Ks[r][c4] = *(const float4*)&Kbase[off];
        *(float4*)&Vs[r][c4] = *(const float4*)&Vbase[off];
    }
    __syncthreads();

    const int d  = tid >> 3;
    const int e0 = (tid & 7) * 4;
    float a0 = 0.f, a1 = 0.f, a2 = 0.f, a3 = 0.f, ks = 0.f;

#pragma unroll 4
    for (int s = 0; s < 128; ++s) {
        const float kv = Ks[s][d];
        ks += kv;
        a0 = fmaf(kv, Vs[s][e0 + 0], a0);
        a1 = fmaf(kv, Vs[s][e0 + 1], a1);
        a2 = fmaf(kv, Vs[s][e0 + 2], a2);
        a3 = fmaf(kv, Vs[s][e0 + 3], a3);
    }

    float* KVout = g_KV + ((size_t)nh * HD + d) * HD + e0;
    atomicAdd(&KVout[0], a0);
    atomicAdd(&KVout[1], a1);
    atomicAdd(&KVout[2], a2);
    atomicAdd(&KVout[3], a3);
    if ((tid & 7) == 0) atomicAdd(&g_Ksum[nh * HD + d], ks);
}

// ---------------------------------------------------------------------------
// Attention apply: reads Q fp32, writes fp16 hi/lo; warp == head.
// ---------------------------------------------------------------------------
__global__ void __launch_bounds__(256)
attn_apply_kernel(const float* __restrict__ Q,
                  __half* __restrict__ Oh, __half* __restrict__ Ol)
{
    __shared__ float KVs[NH * HD * HD];
    __shared__ float KsumS[NH * HD];

    const int row0 = blockIdx.x * 64;
    const int n    = row0 / LSEQ;
    const int tid  = threadIdx.x;
    const int h    = tid >> 5;
    const int e    = tid & 31;

    const float* KVg = g_KV + (size_t)n * NH * HD * HD;
    for (int i = tid; i < NH * HD * HD / 4; i += 256)
        ((float4*)KVs)[i] = ((const float4*)KVg)[i];
    KsumS[tid] = g_Ksum[n * NH * HD + tid];
    __syncthreads();

    const float ks = KsumS[tid];
    const float* kvh = &KVs[h * HD * HD];

    for (int r = 0; r < 64; ++r) {
        const size_t base = (size_t)(row0 + r) * CD;
        const float q = Q[base + tid];
        float z = q * ks;
#pragma unroll
        for (int o = 16; o > 0; o >>= 1) z += __shfl_xor_sync(0xffffffff, z, o);
        z = 1.0f / (z + 1e-6f);
        float acc = 0.0f;
#pragma unroll
        for (int d = 0; d < HD; ++d)
            acc = fmaf(__shfl_sync(0xffffffff, q, d), kvh[d * HD + e], acc);
        const float v = acc * z;
        const __half hh = __float2half_rn(v);
        Oh[base + tid] = hh;
        Ol[base + tid] = __float2half_rn(v - __half2float(hh));
    }
}

// ---------------------------------------------------------------------------
// LayerNorm variants
// ---------------------------------------------------------------------------
__global__ void __launch_bounds__(256)
ln_hilo_kernel(const float* __restrict__ src,
               __half* __restrict__ oh, __half* __restrict__ ol,
               const float* __restrict__ g, const float* __restrict__ b)
{
    const int row  = blockIdx.x * 8 + threadIdx.y;
    const int lane = threadIdx.x;
    const float* p = src + (size_t)row * CD;

    float v[8];
    float s = 0.0f;
#pragma unroll
    for (int i = 0; i < 8; ++i) { v[i] = p[i * 32 + lane]; s += v[i]; }
#pragma unroll
    for (int o = 16; o > 0; o >>= 1) s += __shfl_xor_sync(0xffffffff, s, o);
    const float mu = s * (1.0f / CD);

    float vs = 0.0f;
#pragma unroll
    for (int i = 0; i < 8; ++i) { const float d = v[i] - mu; vs = fmaf(d, d, vs); }
#pragma unroll
    for (int o = 16; o > 0; o >>= 1) vs += __shfl_xor_sync(0xffffffff, vs, o);
    const float rstd = rsqrtf(vs * (1.0f / CD) + 1e-7f);

#pragma unroll
    for (int i = 0; i < 8; ++i) {
        const int c = i * 32 + lane;
        const float r = (v[i] - mu) * rstd * g[c] + b[c];
        const __half hh = __float2half_rn(r);
        oh[(size_t)row * CD + c] = hh;
        ol[(size_t)row * CD + c] = __float2half_rn(r - __half2float(hh));
    }
}

__global__ void __launch_bounds__(256)
ln_res_kernel(const float* __restrict__ src, const float* __restrict__ x,
              float* __restrict__ dst,
              const float* __restrict__ g, const float* __restrict__ b)
{
    const int row  = blockIdx.x * 8 + threadIdx.y;
    const int lane = threadIdx.x;
    const float* p = src + (size_t)row * CD;

    float v[8];
    float s = 0.0f;
#pragma unroll
    for (int i = 0; i < 8; ++i) { v[i] = p[i * 32 + lane]; s += v[i]; }
#pragma unroll
    for (int o = 16; o > 0; o >>= 1) s += __shfl_xor_sync(0xffffffff, s, o);
    const float mu = s * (1.0f / CD);

    float vs = 0.0f;
#pragma unroll
    for (int i = 0; i < 8; ++i) { const float d = v[i] - mu; vs = fmaf(d, d, vs); }
#pragma unroll
    for (int o = 16; o > 0; o >>= 1) vs += __shfl_xor_sync(0xffffffff, vs, o);
    const float rstd = rsqrtf(vs * (1.0f / CD) + 1e-7f);

#pragma unroll
    for (int i = 0; i < 8; ++i) {
        const int c = i * 32 + lane;
        dst[(size_t)row * CD + c] =
            (v[i] - mu) * rstd * g[c] + b[c] + x[(size_t)row * CD + c];
    }
}

// ---------------------------------------------------------------------------
// Launch
// ---------------------------------------------------------------------------
extern "C" void kernel_launch(void* const* d_in, const int* in_sizes, int n_in,
                              void* d_out, int out_size)
{
    const float* x      = (const float*)d_in[0];
    const float* source = (const float*)d_in[1];
    const float* Wq     = (const float*)d_in[2];
    const float* Wk     = (const float*)d_in[3];
    const float* Wv     = (const float*)d_in[4];
    const float* Wmerge = (const float*)d_in[5];
    const float* Wmlp1  = (const float*)d_in[6];
    const float* Wmlp2  = (const float*)d_in[7];
    const float* ln1_g  = (const float*)d_in[8];
    const float* ln1_b  = (const float*)d_in[9];
    const float* ln2_g  = (const float*)d_in[10];
    const float* ln2_b  = (const float*)d_in[11];
    float* out = (float*)d_out;

    float *q, *k, *v;
    __half *xh, *xl, *sh, *sl, *ah, *al, *mh, *ml, *hh, *hl;
    __half *W16q, *W16k, *W16v, *W16m, *W161, *W162;
    cudaGetSymbolAddress((void**)&q, g_q);
    cudaGetSymbolAddress((void**)&k, g_k);
    cudaGetSymbolAddress((void**)&v, g_v);
    cudaGetSymbolAddress((void**)&xh, g_xh);  cudaGetSymbolAddress((void**)&xl, g_xl);
    cudaGetSymbolAddress((void**)&sh, g_sh);  cudaGetSymbolAddress((void**)&sl, g_sl);
    cudaGetSymbolAddress((void**)&ah, g_ah);  cudaGetSymbolAddress((void**)&al, g_al);
    cudaGetSymbolAddress((void**)&mh, g_mh);  cudaGetSymbolAddress((void**)&ml, g_ml);
    cudaGetSymbolAddress((void**)&hh, g_hh);  cudaGetSymbolAddress((void**)&hl, g_hl);
    cudaGetSymbolAddress((void**)&W16q, g_Wq16);
    cudaGetSymbolAddress((void**)&W16k, g_Wk16);
    cudaGetSymbolAddress((void**)&W16v, g_Wv16);
    cudaGetSymbolAddress((void**)&W16m, g_Wm16);
    cudaGetSymbolAddress((void**)&W161, g_W116);
    cudaGetSymbolAddress((void**)&W162, g_W216);

    static bool smem_set = false;
    if (!smem_set) {
        cudaFuncSetAttribute((const void*)gemm_f16p<ACT_ELU1, OUT_F32>,
                             cudaFuncAttributeMaxDynamicSharedMemorySize, SMEM_SZ);
        cudaFuncSetAttribute((const void*)gemm_f16p<ACT_NONE, OUT_F32>,
                             cudaFuncAttributeMaxDynamicSharedMemorySize, SMEM_SZ);
        cudaFuncSetAttribute((const void*)gemm_f16p<ACT_RELU, OUT_HILO>,
                             cudaFuncAttributeMaxDynamicSharedMemorySize, SMEM_SZ);
        smem_set = true;
    }

    const int GM = MTOT / 128;
    const dim3 g256(2, GM);
    const dim3 g512(4, GM);

    // 1: convert activations (x + source) to fp16 hi/lo
    cvt_act_kernel<<<dim3((unsigned)(MC / 4 / 256), 2), 256>>>(x, source);
    // 2: convert all weights to fp16
    cvt_w_kernel<<<640, 256>>>(Wq, Wk, Wv, Wmerge, Wmlp1, Wmlp2);
    // 3: zero accumulators
    zero_kv_kernel<<<(NB * NH * HD * HD + 255) / 256, 256>>>();

    // 4: K = elu(src Wk^T)+1
    gemm_f16p<ACT_ELU1, OUT_F32><<<g256, 256, SMEM_SZ>>>(
        sh, sl, nullptr, nullptr, CD, CD, W16k, k, nullptr, nullptr, CD);
    // 5: V = src Wv^T
    gemm_f16p<ACT_NONE, OUT_F32><<<g256, 256, SMEM_SZ>>>(
        sh, sl, nullptr, nullptr, CD, CD, W16v, v, nullptr, nullptr, CD);
    // 6: Q = elu(x Wq^T)+1   <-- ncu capture slot
    gemm_f16p<ACT_ELU1, OUT_F32><<<g256, 256, SMEM_SZ>>>(
        xh, xl, nullptr, nullptr, CD, CD, W16q, q, nullptr, nullptr, CD);

    // 7: KV / Ksum
    kv_reduce_kernel<<<dim3(NB * NH, LSEQ / 128), 256>>>(k, v);
    // 8: attention apply -> fp16 hi/lo
    attn_apply_kernel<<<MTOT / 64, 256>>>(q, ah, al);

    // 9: msg = attn @ Wmerge^T (fp32 into k)
    gemm_f16p<ACT_NONE, OUT_F32><<<g256, 256, SMEM_SZ>>>(
        ah, al, nullptr, nullptr, CD, CD, W16m, k, nullptr, nullptr, CD);
    // 10: LN1 -> fp16 hi/lo
    ln_hilo_kernel<<<MTOT / 8, dim3(32, 8)>>>(k, mh, ml, ln1_g, ln1_b);

    // 11: h = relu([x | msg] @ Wmlp1^T) -> fp16 hi/lo
    gemm_f16p<ACT_RELU, OUT_HILO><<<g512, 256, SMEM_SZ>>>(
        xh, xl, mh, ml, CD, 2 * CD, W161, nullptr, hh, hl, 2 * CD);

    // 12: msg2 = h @ Wmlp2^T (fp32 into v)
    gemm_f16p<ACT_NONE, OUT_F32><<<g256, 256, SMEM_SZ>>>(
        hh, hl, nullptr, nullptr, 2 * CD, 2 * CD, W162, v, nullptr, nullptr, CD);
    // 13: out = x + LN2(msg2)
    ln_res_kernel<<<MTOT / 8, dim3(32, 8)>>>(v, x, out, ln2_g, ln2_b);
}

// round 6
// speedup vs baseline: 3.6341x; 1.2815x over previous
#include <cuda_runtime.h>
#include <cuda_fp16.h>
#include <math.h>
#include <stdint.h>

// ---------------------------------------------------------------------------
// Problem constants
// ---------------------------------------------------------------------------
#define NB     4
#define LSEQ   8192
#define CD     256
#define NH     8
#define HD     32
#define MTOT   (NB * LSEQ)          // 32768
#define MC     ((size_t)MTOT * CD)  // 8388608
#define MC2    ((size_t)MTOT * 2 * CD)

// ---------------------------------------------------------------------------
// Scratch (device globals)
// ---------------------------------------------------------------------------
__device__ float g_q[MC];                 // Q fp32 (attn input)
__device__ float g_k[MC];                 // K fp32, then msg fp32
__device__ float g_v[MC];                 // V fp32, then msg2 fp32
__device__ float g_KV[NB * NH * HD * HD];
__device__ float g_Ksum[NB * NH * HD];

// fp16 activations (A-side operands, single rounding)
__device__ __half g_x16[MC];              // x
__device__ __half g_s16[MC];              // source
__device__ __half g_a16[MC];              // attn out
__device__ __half g_m16[MC];              // msg after LN1
__device__ __half g_h16[MC2];             // MLP hidden

// fp16 weights (B-side, single rounding)
__device__ __half g_Wq16[CD * CD];
__device__ __half g_Wk16[CD * CD];
__device__ __half g_Wv16[CD * CD];
__device__ __half g_Wm16[CD * CD];
__device__ __half g_W116[2 * CD * 2 * CD];
__device__ __half g_W216[CD * 2 * CD];

// ---------------------------------------------------------------------------
// Helpers
// ---------------------------------------------------------------------------
__device__ __forceinline__ uint32_t smem_u32(const void* p) {
    return (uint32_t)__cvta_generic_to_shared(p);
}
__device__ __forceinline__ void cp16(uint32_t dst, const void* src) {
    asm volatile("cp.async.ca.shared.global [%0], [%1], 16;" :: "r"(dst), "l"(src));
}
__device__ __forceinline__ void cp_commit() {
    asm volatile("cp.async.commit_group;");
}
template <int N>
__device__ __forceinline__ void cp_wait() {
    asm volatile("cp.async.wait_group %0;" :: "n"(N));
}
__device__ __forceinline__ void ldmx4(uint32_t* r, uint32_t addr) {
    asm volatile("ldmatrix.sync.aligned.m8n8.x4.shared.b16 {%0,%1,%2,%3}, [%4];"
                 : "=r"(r[0]), "=r"(r[1]), "=r"(r[2]), "=r"(r[3]) : "r"(addr));
}
__device__ __forceinline__ void mma16816(float* c, const uint32_t* a,
                                         uint32_t b0, uint32_t b1) {
    asm volatile(
        "mma.sync.aligned.m16n8k16.row.col.f32.f16.f16.f32 "
        "{%0,%1,%2,%3}, {%4,%5,%6,%7}, {%8,%9}, {%0,%1,%2,%3};"
        : "+f"(c[0]), "+f"(c[1]), "+f"(c[2]), "+f"(c[3])
        : "r"(a[0]), "r"(a[1]), "r"(a[2]), "r"(a[3]), "r"(b0), "r"(b1));
}
__device__ __forceinline__ uint32_t pack2h(float a, float b) {
    __half2 h = __floats2half2_rn(a, b);
    return *(uint32_t*)&h;
}

// ---------------------------------------------------------------------------
// Activation conversion: fp32 -> fp16.  blockIdx.y: 0 = x, 1 = source.
// ---------------------------------------------------------------------------
__global__ void __launch_bounds__(256)
cvt_act_kernel(const float* __restrict__ x, const float* __restrict__ src)
{
    const size_t i = (size_t)blockIdx.x * blockDim.x + threadIdx.x;  // float4 idx
    const float* s = blockIdx.y ? src : x;
    __half* o = blockIdx.y ? g_s16 : g_x16;
    float4 v = ((const float4*)s)[i];
    uint2 H;
    H.x = pack2h(v.x, v.y);
    H.y = pack2h(v.z, v.w);
    ((uint2*)o)[i] = H;
}

// ---------------------------------------------------------------------------
// Weight conversion: fp32 -> fp16. 163840 float4 total.
// ---------------------------------------------------------------------------
__global__ void __launch_bounds__(256)
cvt_w_kernel(const float* __restrict__ Wq, const float* __restrict__ Wk,
             const float* __restrict__ Wv, const float* __restrict__ Wm,
             const float* __restrict__ W1, const float* __restrict__ W2)
{
    const int i = blockIdx.x * blockDim.x + threadIdx.x;   // float4 index
    const float* s; __half* d; int j;
    if      (i <  16384) { s = Wq; d = g_Wq16; j = i; }
    else if (i <  32768) { s = Wk; d = g_Wk16; j = i - 16384; }
    else if (i <  49152) { s = Wv; d = g_Wv16; j = i - 32768; }
    else if (i <  65536) { s = Wm; d = g_Wm16; j = i - 49152; }
    else if (i < 131072) { s = W1; d = g_W116; j = i - 65536; }
    else                 { s = W2; d = g_W216; j = i - 131072; }
    float4 v = ((const float4*)s)[j];
    uint2 o;
    o.x = pack2h(v.x, v.y);
    o.y = pack2h(v.z, v.w);
    ((uint2*)d)[j] = o;
}

// ---------------------------------------------------------------------------
// Pipelined fp16 GEMM (single pass):
//   C[m,n] = act( sum_k A[m,k] * W[n,k] ),  A fp16, W fp16, fp32 accum.
//   A = [A1 | A2] concat at K1.
//   BM=128, BN=128, BK=32; 8 warps (2x4), warp tile 64x32; cp.async 2-stage.
// ---------------------------------------------------------------------------
enum { ACT_NONE = 0, ACT_ELU1 = 1, ACT_RELU = 2 };
enum { OUT_F32 = 0, OUT_F16 = 1 };

#define BK       32
#define ROWB     80            // smem row stride bytes (64B data + 16B pad)
#define TILE_B   (128 * ROWB)  // 10240
#define STAGE_B  (2 * TILE_B)  // 20480
#define A_OFF    0
#define B_OFF    TILE_B
#define SMEM_SZ  (2 * STAGE_B) // 40960

template <int ACT, int OUT>
__global__ void __launch_bounds__(256, 2)
gemm_f16s(const __half* __restrict__ A1, const __half* __restrict__ A2,
          int K1, int K, const __half* __restrict__ Wh,
          float* __restrict__ Cf, __half* __restrict__ Ch, int NT)
{
    extern __shared__ char smem[];
    const uint32_t sbase = smem_u32(smem);

    const int tid  = threadIdx.x;
    const int wid  = tid >> 5;
    const int lane = tid & 31;
    const int m0   = blockIdx.y * 128;
    const int n0   = blockIdx.x * 128;

    const int wm = (wid >> 2) * 64;
    const int wn = (wid & 3) * 32;

    const int aRow  = wm + (lane & 15);
    const int aHalf = ((lane >> 4) & 1) * 8;
    const int bRow  = wn + (lane & 7) + ((lane >> 4) & 1) * 8;
    const int bHalf = ((lane >> 3) & 1) * 8;

    const int lr  = tid >> 1;
    const int lqb = (tid & 1) * 32;

    float acc[4][4][4];
#pragma unroll
    for (int i = 0; i < 4; ++i)
#pragma unroll
        for (int j = 0; j < 4; ++j)
#pragma unroll
            for (int r = 0; r < 4; ++r) acc[i][j][r] = 0.0f;

    const int KT = K / BK;

    auto prefetch = [&](int kt, int st) {
        const int kg0 = kt * BK;
        const __half* pA; int lda, kb;
        if (A2 != nullptr && kg0 >= K1) { pA = A2; lda = K - K1; kb = kg0 - K1; }
        else                            { pA = A1; lda = K1;     kb = kg0; }

        const uint32_t sd = sbase + st * STAGE_B + lr * ROWB + lqb;
        const char* gA = (const char*)(pA + (size_t)(m0 + lr) * lda + kb) + lqb;
        const char* gB = (const char*)(Wh + (size_t)(n0 + lr) * K + kg0) + lqb;
        cp16(sd + A_OFF, gA);  cp16(sd + A_OFF + 16, gA + 16);
        cp16(sd + B_OFF, gB);  cp16(sd + B_OFF + 16, gB + 16);
        cp_commit();
    };

    prefetch(0, 0);

    for (int kt = 0; kt < KT; ++kt) {
        const int st = kt & 1;
        if (kt + 1 < KT) { prefetch(kt + 1, st ^ 1); cp_wait<1>(); }
        else             { cp_wait<0>(); }
        __syncthreads();

        const uint32_t base = sbase + st * STAGE_B;
#pragma unroll
        for (int ks = 0; ks < 2; ++ks) {
            uint32_t bf[2][4];
#pragma unroll
            for (int nf = 0; nf < 2; ++nf)
                ldmx4(bf[nf], base + B_OFF + (uint32_t)((bRow + nf * 16) * ROWB) +
                              (uint32_t)(ks * 16 + bHalf) * 2);
            uint32_t af[4][4];
#pragma unroll
            for (int mf = 0; mf < 4; ++mf)
                ldmx4(af[mf], base + A_OFF + (uint32_t)((aRow + mf * 16) * ROWB) +
                              (uint32_t)(ks * 16 + aHalf) * 2);
#pragma unroll
            for (int mf = 0; mf < 4; ++mf)
#pragma unroll
                for (int nr = 0; nr < 4; ++nr)
                    mma16816(acc[mf][nr], af[mf], bf[nr >> 1][(nr & 1) * 2],
                             bf[nr >> 1][(nr & 1) * 2 + 1]);
        }
        __syncthreads();
    }

    // ---- epilogue ----
    const int g  = lane >> 2;
    const int qd = lane & 3;
#pragma unroll
    for (int mf = 0; mf < 4; ++mf) {
#pragma unroll
        for (int nr = 0; nr < 4; ++nr) {
#pragma unroll
            for (int half = 0; half < 2; ++half) {
                const int row = m0 + wm + mf * 16 + g + half * 8;
                const int col = n0 + wn + nr * 8 + qd * 2;
                float v0 = acc[mf][nr][half * 2 + 0];
                float v1 = acc[mf][nr][half * 2 + 1];
                if (ACT == ACT_ELU1) {
                    v0 = (v0 > 0.f) ? v0 + 1.f : expf(v0);
                    v1 = (v1 > 0.f) ? v1 + 1.f : expf(v1);
                }
                if (ACT == ACT_RELU) { v0 = fmaxf(v0, 0.f); v1 = fmaxf(v1, 0.f); }
                const size_t off = (size_t)row * NT + col;
                if (OUT == OUT_F32) {
                    float2 o; o.x = v0; o.y = v1;
                    *(float2*)&Cf[off] = o;
                } else {
                    *(uint32_t*)&Ch[off] = pack2h(v0, v1);
                }
            }
        }
    }
}

// ---------------------------------------------------------------------------
// Zero KV / Ksum accumulators
// ---------------------------------------------------------------------------
__global__ void zero_kv_kernel()
{
    int i = blockIdx.x * blockDim.x + threadIdx.x;
    if (i < NB * NH * HD * HD) g_KV[i] = 0.0f;
    if (i < NB * NH * HD)      g_Ksum[i] = 0.0f;
}

// ---------------------------------------------------------------------------
// KV reduce
// ---------------------------------------------------------------------------
__global__ void __launch_bounds__(256)
kv_reduce_kernel(const float* __restrict__ Kmat, const float* __restrict__ Vmat)
{
    __shared__ float Ks[128][HD];
    __shared__ float Vs[128][HD];

    const int nh = blockIdx.x;
    const int n  = nh / NH;
    const int h  = nh % NH;
    const int s0 = blockIdx.y * 128;
    const int tid = threadIdx.x;

    const float* Kbase = Kmat + (size_t)n * LSEQ * CD + (size_t)h * HD;
    const float* Vbase = Vmat + (size_t)n * LSEQ * CD + (size_t)h * HD;

    for (int i = tid; i < 128 * 8; i += 256) {
        const int r  = i >> 3;
        const int c4 = (i & 7) * 4;
        const size_t off = (size_t)(s0 + r) * CD + c4;
        *(float4*)&Ks[r][c4] = *(const float4*)&Kbase[off];
        *(float4*)&Vs[r][c4] = *(const float4*)&Vbase[off];
    }
    __syncthreads();

    const int d  = tid >> 3;
    const int e0 = (tid & 7) * 4;
    float a0 = 0.f, a1 = 0.f, a2 = 0.f, a3 = 0.f, ks = 0.f;

#pragma unroll 4
    for (int s = 0; s < 128; ++s) {
        const float kv = Ks[s][d];
        ks += kv;
        a0 = fmaf(kv, Vs[s][e0 + 0], a0);
        a1 = fmaf(kv, Vs[s][e0 + 1], a1);
        a2 = fmaf(kv, Vs[s][e0 + 2], a2);
        a3 = fmaf(kv, Vs[s][e0 + 3], a3);
    }

    float* KVout = g_KV + ((size_t)nh * HD + d) * HD + e0;
    atomicAdd(&KVout[0], a0);
    atomicAdd(&KVout[1], a1);
    atomicAdd(&KVout[2], a2);
    atomicAdd(&KVout[3], a3);
    if ((tid & 7) == 0) atomicAdd(&g_Ksum[nh * HD + d], ks);
}

// ---------------------------------------------------------------------------
// Attention apply: reads Q fp32, writes fp16; warp == head.
// ---------------------------------------------------------------------------
__global__ void __launch_bounds__(256)
attn_apply_kernel(const float* __restrict__ Q, __half* __restrict__ O)
{
    __shared__ float KVs[NH * HD * HD];
    __shared__ float KsumS[NH * HD];

    const int row0 = blockIdx.x * 64;
    const int n    = row0 / LSEQ;
    const int tid  = threadIdx.x;
    const int h    = tid >> 5;
    const int e    = tid & 31;

    const float* KVg = g_KV + (size_t)n * NH * HD * HD;
    for (int i = tid; i < NH * HD * HD / 4; i += 256)
        ((float4*)KVs)[i] = ((const float4*)KVg)[i];
    KsumS[tid] = g_Ksum[n * NH * HD + tid];
    __syncthreads();

    const float ks = KsumS[tid];
    const float* kvh = &KVs[h * HD * HD];

    for (int r = 0; r < 64; ++r) {
        const size_t base = (size_t)(row0 + r) * CD;
        const float q = Q[base + tid];
        float z = q * ks;
#pragma unroll
        for (int o = 16; o > 0; o >>= 1) z += __shfl_xor_sync(0xffffffff, z, o);
        z = 1.0f / (z + 1e-6f);
        float acc = 0.0f;
#pragma unroll
        for (int d = 0; d < HD; ++d)
            acc = fmaf(__shfl_sync(0xffffffff, q, d), kvh[d * HD + e], acc);
        O[base + tid] = __float2half_rn(acc * z);
    }
}

// ---------------------------------------------------------------------------
// LayerNorm variants
// ---------------------------------------------------------------------------
__global__ void __launch_bounds__(256)
ln_f16_kernel(const float* __restrict__ src, __half* __restrict__ o,
              const float* __restrict__ g, const float* __restrict__ b)
{
    const int row  = blockIdx.x * 8 + threadIdx.y;
    const int lane = threadIdx.x;
    const float* p = src + (size_t)row * CD;

    float v[8];
    float s = 0.0f;
#pragma unroll
    for (int i = 0; i < 8; ++i) { v[i] = p[i * 32 + lane]; s += v[i]; }
#pragma unroll
    for (int of = 16; of > 0; of >>= 1) s += __shfl_xor_sync(0xffffffff, s, of);
    const float mu = s * (1.0f / CD);

    float vs = 0.0f;
#pragma unroll
    for (int i = 0; i < 8; ++i) { const float d = v[i] - mu; vs = fmaf(d, d, vs); }
#pragma unroll
    for (int of = 16; of > 0; of >>= 1) vs += __shfl_xor_sync(0xffffffff, vs, of);
    const float rstd = rsqrtf(vs * (1.0f / CD) + 1e-7f);

#pragma unroll
    for (int i = 0; i < 8; ++i) {
        const int c = i * 32 + lane;
        o[(size_t)row * CD + c] =
            __float2half_rn((v[i] - mu) * rstd * g[c] + b[c]);
    }
}

__global__ void __launch_bounds__(256)
ln_res_kernel(const float* __restrict__ src, const float* __restrict__ x,
              float* __restrict__ dst,
              const float* __restrict__ g, const float* __restrict__ b)
{
    const int row  = blockIdx.x * 8 + threadIdx.y;
    const int lane = threadIdx.x;
    const float* p = src + (size_t)row * CD;

    float v[8];
    float s = 0.0f;
#pragma unroll
    for (int i = 0; i < 8; ++i) { v[i] = p[i * 32 + lane]; s += v[i]; }
#pragma unroll
    for (int of = 16; of > 0; of >>= 1) s += __shfl_xor_sync(0xffffffff, s, of);
    const float mu = s * (1.0f / CD);

    float vs = 0.0f;
#pragma unroll
    for (int i = 0; i < 8; ++i) { const float d = v[i] - mu; vs = fmaf(d, d, vs); }
#pragma unroll
    for (int of = 16; of > 0; of >>= 1) vs += __shfl_xor_sync(0xffffffff, vs, of);
    const float rstd = rsqrtf(vs * (1.0f / CD) + 1e-7f);

#pragma unroll
    for (int i = 0; i < 8; ++i) {
        const int c = i * 32 + lane;
        dst[(size_t)row * CD + c] =
            (v[i] - mu) * rstd * g[c] + b[c] + x[(size_t)row * CD + c];
    }
}

// ---------------------------------------------------------------------------
// Launch
// ---------------------------------------------------------------------------
extern "C" void kernel_launch(void* const* d_in, const int* in_sizes, int n_in,
                              void* d_out, int out_size)
{
    const float* x      = (const float*)d_in[0];
    const float* source = (const float*)d_in[1];
    const float* Wq     = (const float*)d_in[2];
    const float* Wk     = (const float*)d_in[3];
    const float* Wv     = (const float*)d_in[4];
    const float* Wmerge = (const float*)d_in[5];
    const float* Wmlp1  = (const float*)d_in[6];
    const float* Wmlp2  = (const float*)d_in[7];
    const float* ln1_g  = (const float*)d_in[8];
    const float* ln1_b  = (const float*)d_in[9];
    const float* ln2_g  = (const float*)d_in[10];
    const float* ln2_b  = (const float*)d_in[11];
    float* out = (float*)d_out;

    float *q, *k, *v;
    __half *x16, *s16, *a16, *m16, *h16;
    __half *W16q, *W16k, *W16v, *W16m, *W161, *W162;
    cudaGetSymbolAddress((void**)&q, g_q);
    cudaGetSymbolAddress((void**)&k, g_k);
    cudaGetSymbolAddress((void**)&v, g_v);
    cudaGetSymbolAddress((void**)&x16, g_x16);
    cudaGetSymbolAddress((void**)&s16, g_s16);
    cudaGetSymbolAddress((void**)&a16, g_a16);
    cudaGetSymbolAddress((void**)&m16, g_m16);
    cudaGetSymbolAddress((void**)&h16, g_h16);
    cudaGetSymbolAddress((void**)&W16q, g_Wq16);
    cudaGetSymbolAddress((void**)&W16k, g_Wk16);
    cudaGetSymbolAddress((void**)&W16v, g_Wv16);
    cudaGetSymbolAddress((void**)&W16m, g_Wm16);
    cudaGetSymbolAddress((void**)&W161, g_W116);
    cudaGetSymbolAddress((void**)&W162, g_W216);

    static bool smem_set = false;
    if (!smem_set) {
        cudaFuncSetAttribute((const void*)gemm_f16s<ACT_ELU1, OUT_F32>,
                             cudaFuncAttributeMaxDynamicSharedMemorySize, SMEM_SZ);
        cudaFuncSetAttribute((const void*)gemm_f16s<ACT_NONE, OUT_F32>,
                             cudaFuncAttributeMaxDynamicSharedMemorySize, SMEM_SZ);
        cudaFuncSetAttribute((const void*)gemm_f16s<ACT_RELU, OUT_F16>,
                             cudaFuncAttributeMaxDynamicSharedMemorySize, SMEM_SZ);
        smem_set = true;
    }

    const int GM = MTOT / 128;
    const dim3 g256(2, GM);
    const dim3 g512(4, GM);

    // 1: convert activations (x + source) to fp16
    cvt_act_kernel<<<dim3((unsigned)(MC / 4 / 256), 2), 256>>>(x, source);
    // 2: convert all weights to fp16
    cvt_w_kernel<<<640, 256>>>(Wq, Wk, Wv, Wmerge, Wmlp1, Wmlp2);
    // 3: zero accumulators
    zero_kv_kernel<<<(NB * NH * HD * HD + 255) / 256, 256>>>();

    // 4: K = elu(src Wk^T)+1
    gemm_f16s<ACT_ELU1, OUT_F32><<<g256, 256, SMEM_SZ>>>(
        s16, nullptr, CD, CD, W16k, k, nullptr, CD);
    // 5: V = src Wv^T
    gemm_f16s<ACT_NONE, OUT_F32><<<g256, 256, SMEM_SZ>>>(
        s16, nullptr, CD, CD, W16v, v, nullptr, CD);
    // 6: Q = elu(x Wq^T)+1   <-- ncu capture slot
    gemm_f16s<ACT_ELU1, OUT_F32><<<g256, 256, SMEM_SZ>>>(
        x16, nullptr, CD, CD, W16q, q, nullptr, CD);

    // 7: KV / Ksum
    kv_reduce_kernel<<<dim3(NB * NH, LSEQ / 128), 256>>>(k, v);
    // 8: attention apply -> fp16
    attn_apply_kernel<<<MTOT / 64, 256>>>(q, a16);

    // 9: msg = attn @ Wmerge^T (fp32 into k)
    gemm_f16s<ACT_NONE, OUT_F32><<<g256, 256, SMEM_SZ>>>(
        a16, nullptr, CD, CD, W16m, k, nullptr, CD);
    // 10: LN1 -> fp16
    ln_f16_kernel<<<MTOT / 8, dim3(32, 8)>>>(k, m16, ln1_g, ln1_b);

    // 11: h = relu([x | msg] @ Wmlp1^T) -> fp16
    gemm_f16s<ACT_RELU, OUT_F16><<<g512, 256, SMEM_SZ>>>(
        x16, m16, CD, 2 * CD, W161, nullptr, h16, 2 * CD);

    // 12: msg2 = h @ Wmlp2^T (fp32 into v)
    gemm_f16s<ACT_NONE, OUT_F32><<<g256, 256, SMEM_SZ>>>(
        h16, nullptr, 2 * CD, 2 * CD, W162, v, nullptr, CD);
    // 13: out = x + LN2(msg2)
    ln_res_kernel<<<MTOT / 8, dim3(32, 8)>>>(v, x, out, ln2_g, ln2_b);
}